// round 13
// baseline (speedup 1.0000x reference)
#include <cuda_runtime.h>
#include <cstdint>

#define B_   8
#define N_   784
#define DIM_ 384
#define H_   12
#define HD_  32
#define GS_  28
#define ROWS_ (B_*N_)   // 6272
#define SCALE_ 0.28867513459481287f   // 12^-0.5

__device__ float g_q[B_*H_*N_*HD_];
__device__ float g_k[B_*H_*N_*HD_];
__device__ float g_v[B_*H_*N_*HD_];
__device__ float g_att[B_*N_*DIM_];      // attn output, fp32
__device__ float g_pos[H_*N_*N_];        // normalized positional scores (tf32 bits)

// ---------------------------------------------------------------------------
// helpers
// ---------------------------------------------------------------------------
__device__ __forceinline__ unsigned f2tf(float f) {
    unsigned r; asm("cvt.rna.tf32.f32 %0, %1;" : "=r"(r) : "f"(f)); return r;
}
__device__ __forceinline__ void mma8(float4& d,
                                     unsigned a0, unsigned a1, unsigned a2, unsigned a3,
                                     unsigned b0, unsigned b1) {
    asm volatile("mma.sync.aligned.m16n8k8.row.col.f32.tf32.tf32.f32 "
                 "{%0,%1,%2,%3}, {%4,%5,%6,%7}, {%8,%9}, {%0,%1,%2,%3};\n"
                 : "+f"(d.x), "+f"(d.y), "+f"(d.z), "+f"(d.w)
                 : "r"(a0), "r"(a1), "r"(a2), "r"(a3), "r"(b0), "r"(b1));
}
__device__ __forceinline__ void cpa16(void* s, const void* g, bool pred) {
    unsigned sa = (unsigned)__cvta_generic_to_shared(s);
    int sz = pred ? 16 : 0;
    asm volatile("cp.async.cg.shared.global [%0], [%1], 16, %2;\n"
                 :: "r"(sa), "l"(g), "r"(sz) : "memory");
}
__device__ __forceinline__ void cpa_commit() {
    asm volatile("cp.async.commit_group;\n" ::: "memory");
}

// ---------------------------------------------------------------------------
// Kernel 1: normalized positional softmax  pos[h][n][m]  (writes tf32 bits)
// ---------------------------------------------------------------------------
__global__ void pos_kernel(const float* __restrict__ W_pos,
                           const float* __restrict__ b_pos) {
    int hn = blockIdx.x;
    int h = hn / N_, n = hn - h * N_;
    int nx = n % GS_, ny = n / GS_;
    float w0 = W_pos[h*3+0], w1 = W_pos[h*3+1], w2 = W_pos[h*3+2], bp = b_pos[h];
    int t = threadIdx.x;

    float lg[4];
    float lmax = -1e30f;
#pragma unroll
    for (int i = 0; i < 4; i++) {
        int m = t + i * 256;
        if (m < N_) {
            int mx = m % GS_, my = m / GS_;
            float dx = (float)(mx - nx), dy = (float)(my - ny);
            float v = fmaf(w2, dx*dx + dy*dy, fmaf(w1, dy, fmaf(w0, dx, bp)));
            lg[i] = v;
            lmax = fmaxf(lmax, v);
        } else lg[i] = -1e30f;
    }
    __shared__ float sred[8];
    __shared__ float ssum[8];
#pragma unroll
    for (int o = 16; o > 0; o >>= 1)
        lmax = fmaxf(lmax, __shfl_xor_sync(0xffffffffu, lmax, o));
    if ((t & 31) == 0) sred[t >> 5] = lmax;
    __syncthreads();
    float bmax = fmaxf(fmaxf(fmaxf(sred[0], sred[1]), fmaxf(sred[2], sred[3])),
                       fmaxf(fmaxf(sred[4], sred[5]), fmaxf(sred[6], sred[7])));

    float e[4]; float lsum = 0.f;
#pragma unroll
    for (int i = 0; i < 4; i++) { e[i] = __expf(lg[i] - bmax); lsum += e[i]; }
#pragma unroll
    for (int o = 16; o > 0; o >>= 1)
        lsum += __shfl_xor_sync(0xffffffffu, lsum, o);
    if ((t & 31) == 0) ssum[t >> 5] = lsum;
    __syncthreads();
    float tot = ((ssum[0]+ssum[1])+(ssum[2]+ssum[3]))+((ssum[4]+ssum[5])+(ssum[6]+ssum[7]));
    float inv = 1.f / tot;

    float* outp = g_pos + (size_t)hn * N_;
#pragma unroll
    for (int i = 0; i < 4; i++) {
        int m = t + i * 256;
        if (m < N_) outp[m] = __uint_as_float(f2tf(e[i] * inv));
    }
}

// ---------------------------------------------------------------------------
// Kernel 2: fused QKV tf32 GEMM (champion config: 64x64, 128 thr, reg-prefetch)
// ---------------------------------------------------------------------------
#define GSTR 36
__global__ __launch_bounds__(128) void gemm_qkv(
    const float* __restrict__ X, const float* __restrict__ Wq,
    const float* __restrict__ Wk, const float* __restrict__ Wv)
{
    __shared__ unsigned Xs[2][64][GSTR];
    __shared__ unsigned Ws[2][64][GSTR];

    int t = threadIdx.x, w = t >> 5, lane = t & 31;
    int ly = lane >> 2, lx = lane & 3;
    int wr = w >> 1, wc = w & 1;
    int row0 = blockIdx.y * 64, col0 = blockIdx.x * 64;
    int wsel = col0 / DIM_;
    int colw = col0 - wsel * DIM_;
    const float* W = (wsel == 0) ? Wq : (wsel == 1) ? Wk : Wv;
    float* Op = (wsel == 0) ? g_q : (wsel == 1) ? g_k : g_v;
    float scale = (wsel == 0) ? SCALE_ : 1.f;

    float4 rx[4], rw[4];
#pragma unroll
    for (int l = 0; l < 4; l++) {
        int idx = t + l * 128;
        int r = idx >> 3, kq = (idx & 7) << 2;
        rx[l] = *(const float4*)&X[(size_t)(row0 + r) * DIM_ + kq];
        rw[l] = *(const float4*)&W[(size_t)(colw + r) * DIM_ + kq];
    }
#pragma unroll
    for (int l = 0; l < 4; l++) {
        int idx = t + l * 128;
        int r = idx >> 3, kq = (idx & 7) << 2;
        *(uint4*)&Xs[0][r][kq] = make_uint4(f2tf(rx[l].x), f2tf(rx[l].y), f2tf(rx[l].z), f2tf(rx[l].w));
        *(uint4*)&Ws[0][r][kq] = make_uint4(f2tf(rw[l].x), f2tf(rw[l].y), f2tf(rw[l].z), f2tf(rw[l].w));
    }
    __syncthreads();

    float4 acc[2][4];
#pragma unroll
    for (int i = 0; i < 2; i++)
#pragma unroll
        for (int j = 0; j < 4; j++) acc[i][j] = make_float4(0.f, 0.f, 0.f, 0.f);

    for (int ki = 0; ki < 12; ki++) {
        int cur = ki & 1;
        if (ki < 11) {
            int k0 = (ki + 1) * 32;
#pragma unroll
            for (int l = 0; l < 4; l++) {
                int idx = t + l * 128;
                int r = idx >> 3, kq = (idx & 7) << 2;
                rx[l] = *(const float4*)&X[(size_t)(row0 + r) * DIM_ + k0 + kq];
                rw[l] = *(const float4*)&W[(size_t)(colw + r) * DIM_ + k0 + kq];
            }
        }
#pragma unroll
        for (int kk = 0; kk < 4; kk++) {
            int K0 = kk * 8;
            unsigned a[2][4];
#pragma unroll
            for (int mi = 0; mi < 2; mi++) {
                int rb = wr * 32 + mi * 16 + ly;
                a[mi][0] = Xs[cur][rb][K0 + lx];
                a[mi][1] = Xs[cur][rb + 8][K0 + lx];
                a[mi][2] = Xs[cur][rb][K0 + lx + 4];
                a[mi][3] = Xs[cur][rb + 8][K0 + lx + 4];
            }
#pragma unroll
            for (int nt = 0; nt < 4; nt++) {
                int cb = wc * 32 + nt * 8 + ly;
                unsigned b0 = Ws[cur][cb][K0 + lx];
                unsigned b1 = Ws[cur][cb][K0 + lx + 4];
                mma8(acc[0][nt], a[0][0], a[0][1], a[0][2], a[0][3], b0, b1);
                mma8(acc[1][nt], a[1][0], a[1][1], a[1][2], a[1][3], b0, b1);
            }
        }
        if (ki < 11) {
            int nxt = (ki + 1) & 1;
#pragma unroll
            for (int l = 0; l < 4; l++) {
                int idx = t + l * 128;
                int r = idx >> 3, kq = (idx & 7) << 2;
                *(uint4*)&Xs[nxt][r][kq] = make_uint4(f2tf(rx[l].x), f2tf(rx[l].y), f2tf(rx[l].z), f2tf(rx[l].w));
                *(uint4*)&Ws[nxt][r][kq] = make_uint4(f2tf(rw[l].x), f2tf(rw[l].y), f2tf(rw[l].z), f2tf(rw[l].w));
            }
        }
        __syncthreads();
    }

    int h = (colw + wc * 32) >> 5;
#pragma unroll
    for (int mi = 0; mi < 2; mi++) {
        int row = row0 + wr * 32 + mi * 16 + ly;
#pragma unroll
        for (int nt = 0; nt < 4; nt++) {
            int d = nt * 8 + lx * 2;
            {
                int b = row / N_, n = row - b * N_;
                float2 v;
                v.x = __uint_as_float(f2tf(acc[mi][nt].x * scale));
                v.y = __uint_as_float(f2tf(acc[mi][nt].y * scale));
                *(float2*)&Op[(((size_t)(b * H_ + h)) * N_ + n) * HD_ + d] = v;
            }
            {
                int row2 = row + 8;
                int b = row2 / N_, n = row2 - b * N_;
                float2 v;
                v.x = __uint_as_float(f2tf(acc[mi][nt].z * scale));
                v.y = __uint_as_float(f2tf(acc[mi][nt].w * scale));
                *(float2*)&Op[(((size_t)(b * H_ + h)) * N_ + n) * HD_ + d] = v;
            }
        }
    }
}

// ---------------------------------------------------------------------------
// Kernel 2b: out-projection tf32 GEMM (champion config), +bias, fp32
// ---------------------------------------------------------------------------
__global__ __launch_bounds__(128) void gemm_out(
    const float* __restrict__ W, const float* __restrict__ bias,
    float* __restrict__ OUTp)
{
    __shared__ unsigned Xs[2][64][GSTR];
    __shared__ unsigned Ws[2][64][GSTR];

    int t = threadIdx.x, w = t >> 5, lane = t & 31;
    int ly = lane >> 2, lx = lane & 3;
    int wr = w >> 1, wc = w & 1;
    int row0 = blockIdx.y * 64, col0 = blockIdx.x * 64;
    const float* X = g_att;

    float4 rx[4], rw[4];
#pragma unroll
    for (int l = 0; l < 4; l++) {
        int idx = t + l * 128;
        int r = idx >> 3, kq = (idx & 7) << 2;
        rx[l] = *(const float4*)&X[(size_t)(row0 + r) * DIM_ + kq];
        rw[l] = *(const float4*)&W[(size_t)(col0 + r) * DIM_ + kq];
    }
#pragma unroll
    for (int l = 0; l < 4; l++) {
        int idx = t + l * 128;
        int r = idx >> 3, kq = (idx & 7) << 2;
        *(uint4*)&Xs[0][r][kq] = make_uint4(f2tf(rx[l].x), f2tf(rx[l].y), f2tf(rx[l].z), f2tf(rx[l].w));
        *(uint4*)&Ws[0][r][kq] = make_uint4(f2tf(rw[l].x), f2tf(rw[l].y), f2tf(rw[l].z), f2tf(rw[l].w));
    }
    __syncthreads();

    float4 acc[2][4];
#pragma unroll
    for (int i = 0; i < 2; i++)
#pragma unroll
        for (int j = 0; j < 4; j++) acc[i][j] = make_float4(0.f, 0.f, 0.f, 0.f);

    for (int ki = 0; ki < 12; ki++) {
        int cur = ki & 1;
        if (ki < 11) {
            int k0 = (ki + 1) * 32;
#pragma unroll
            for (int l = 0; l < 4; l++) {
                int idx = t + l * 128;
                int r = idx >> 3, kq = (idx & 7) << 2;
                rx[l] = *(const float4*)&X[(size_t)(row0 + r) * DIM_ + k0 + kq];
                rw[l] = *(const float4*)&W[(size_t)(col0 + r) * DIM_ + k0 + kq];
            }
        }
#pragma unroll
        for (int kk = 0; kk < 4; kk++) {
            int K0 = kk * 8;
            unsigned a[2][4];
#pragma unroll
            for (int mi = 0; mi < 2; mi++) {
                int rb = wr * 32 + mi * 16 + ly;
                a[mi][0] = Xs[cur][rb][K0 + lx];
                a[mi][1] = Xs[cur][rb + 8][K0 + lx];
                a[mi][2] = Xs[cur][rb][K0 + lx + 4];
                a[mi][3] = Xs[cur][rb + 8][K0 + lx + 4];
            }
#pragma unroll
            for (int nt = 0; nt < 4; nt++) {
                int cb = wc * 32 + nt * 8 + ly;
                unsigned b0 = Ws[cur][cb][K0 + lx];
                unsigned b1 = Ws[cur][cb][K0 + lx + 4];
                mma8(acc[0][nt], a[0][0], a[0][1], a[0][2], a[0][3], b0, b1);
                mma8(acc[1][nt], a[1][0], a[1][1], a[1][2], a[1][3], b0, b1);
            }
        }
        if (ki < 11) {
            int nxt = (ki + 1) & 1;
#pragma unroll
            for (int l = 0; l < 4; l++) {
                int idx = t + l * 128;
                int r = idx >> 3, kq = (idx & 7) << 2;
                *(uint4*)&Xs[nxt][r][kq] = make_uint4(f2tf(rx[l].x), f2tf(rx[l].y), f2tf(rx[l].z), f2tf(rx[l].w));
                *(uint4*)&Ws[nxt][r][kq] = make_uint4(f2tf(rw[l].x), f2tf(rw[l].y), f2tf(rw[l].z), f2tf(rw[l].w));
            }
        }
        __syncthreads();
    }

#pragma unroll
    for (int mi = 0; mi < 2; mi++) {
        int row = row0 + wr * 32 + mi * 16 + ly;
#pragma unroll
        for (int nt = 0; nt < 4; nt++) {
            int col = col0 + wc * 32 + nt * 8 + lx * 2;
            float b0 = bias[col], b1 = bias[col + 1];
            float2 v0; v0.x = acc[mi][nt].x + b0; v0.y = acc[mi][nt].y + b1;
            *(float2*)&OUTp[(size_t)row * DIM_ + col] = v0;
            float2 v1; v1.x = acc[mi][nt].z + b0; v1.y = acc[mi][nt].w + b1;
            *(float2*)&OUTp[(size_t)(row + 8) * DIM_ + col] = v1;
        }
    }
}

// ---------------------------------------------------------------------------
// Kernel 3: fused gated attention — P1 smem eliminated via intra-warp
// shuffles (C-frag -> A-frag permutation in registers). ASmem 56.3 KB ->
// 4 blocks/SM. Warp-private P2, one block barrier per iteration.
// ---------------------------------------------------------------------------
#define QSTR 36
#define VSTR 40
#define PSTR 68
struct ASmem {
    unsigned P2[64][PSTR];       // pos tile (warp-private rows; Q staging at start)
    unsigned Ks[2][64][QSTR];
    unsigned Vs[2][64][VSTR];
};   // 56320 B -> 4 blocks/SM

__global__ __launch_bounds__(128) void attn_kernel(const float* __restrict__ gating) {
    extern __shared__ char sraw[];
    ASmem& S = *reinterpret_cast<ASmem*>(sraw);

    int t = threadIdx.x, w = t >> 5, lane = t & 31;
    int ly = lane >> 2, lx = lane & 3;
    int bh = blockIdx.y;
    int b = bh / H_, h = bh - b * H_;
    int q0 = blockIdx.x * 64;
    int R0 = w * 16;
    const unsigned FULL = 0xffffffffu;
    int srcA = ly * 4 + (lx >> 1);      // shuffle source for col lx
    int srcB = srcA + 2;                // shuffle source for col lx+4
    bool hiSel = (lx & 1);

    const float* Qg   = g_q + (size_t)bh * N_ * HD_;
    const float* Kg   = g_k + (size_t)bh * N_ * HD_;
    const float* Vg   = g_v + (size_t)bh * N_ * HD_;
    const float* POSg = g_pos + (size_t)h * N_ * N_;

    float gate = 1.f / (1.f + __expf(-gating[h]));

    // ---- prologue G0 (block-wide): Q staged into P2 rows + KV[0]
#pragma unroll
    for (int l = 0; l < 4; l++) {
        int idx = t + l * 128;
        int r = idx >> 3, dq = (idx & 7) << 2;
        cpa16(&S.P2[r][dq], &Qg[(size_t)(q0 + r) * HD_ + dq], q0 + r < N_);
        bool mv = r < N_;   // m0 = 0
        cpa16(&S.Ks[0][r][dq], &Kg[(size_t)r * HD_ + dq], mv);
        cpa16(&S.Vs[0][r][dq], &Vg[(size_t)r * HD_ + dq], mv);
    }
    cpa_commit();
    asm volatile("cp.async.wait_group 0;\n" ::: "memory");
    __syncthreads();

    // Q fragments -> registers (warp reads only its own rows)
    unsigned qf[4][4];
#pragma unroll
    for (int kk = 0; kk < 4; kk++) {
        int K0 = kk * 8;
        qf[kk][0] = S.P2[R0 + ly][K0 + lx];
        qf[kk][1] = S.P2[R0 + ly + 8][K0 + lx];
        qf[kk][2] = S.P2[R0 + ly][K0 + lx + 4];
        qf[kk][3] = S.P2[R0 + ly + 8][K0 + lx + 4];
    }
    __syncwarp();   // this warp done reading its Q rows; refill below is same-warp rows

    // P2[0]: warp-private refill (16 rows x 64 cols per warp, 8 float4/lane)
#pragma unroll
    for (int l = 0; l < 8; l++) {
        int idx = lane + l * 32;
        int rr = idx >> 4, cq = (idx & 15) << 2;
        cpa16(&S.P2[R0 + rr][cq], &POSg[(size_t)(q0 + R0 + rr) * N_ + cq],
              (q0 + R0 + rr < N_) && (cq < N_));
    }
    cpa_commit();   // per-thread FIFO: { P2[0] }

    float4 opat[4], opos[4];
#pragma unroll
    for (int i = 0; i < 4; i++) { opat[i] = make_float4(0.f,0.f,0.f,0.f); opos[i] = opat[i]; }
    float rs0 = 0.f, rs1 = 0.f;

    for (int it = 0; it < 13; it++) {
        int cur = it & 1;
        int m1 = (it + 1) * 64;
        // FIFO at top: { P2[it] }
        if (it < 12) {
            int nxt = (it + 1) & 1;
#pragma unroll
            for (int l = 0; l < 4; l++) {
                int idx = t + l * 128;
                int r = idx >> 3, dq = (idx & 7) << 2;
                bool mv = m1 + r < N_;
                cpa16(&S.Ks[nxt][r][dq], &Kg[(size_t)(m1 + r) * HD_ + dq], mv);
                cpa16(&S.Vs[nxt][r][dq], &Vg[(size_t)(m1 + r) * HD_ + dq], mv);
            }
            cpa_commit();   // FIFO: { P2[it], KV[it+1] }
        }

        // S = Q K^T  (16 x 64 per warp); Ks[cur] visible from last iter's barrier
        float4 sacc[8];
#pragma unroll
        for (int i = 0; i < 8; i++) sacc[i] = make_float4(0.f,0.f,0.f,0.f);
#pragma unroll
        for (int kk = 0; kk < 4; kk++) {
            int K0 = kk * 8;
#pragma unroll
            for (int nt = 0; nt < 8; nt++) {
                unsigned b0 = S.Ks[cur][nt * 8 + ly][K0 + lx];
                unsigned b1 = S.Ks[cur][nt * 8 + ly][K0 + lx + 4];
                mma8(sacc[nt], qf[kk][0], qf[kk][1], qf[kk][2], qf[kk][3], b0, b1);
            }
        }

        // exp + rowsum, tf32 bits kept in registers (pe = C-fragment layout)
        int m0 = it * 64;
        unsigned pe[8][4];
#pragma unroll
        for (int nt = 0; nt < 8; nt++) {
            int mc = m0 + nt * 8 + lx * 2;
            bool mv = (mc < N_);
            float ex = mv ? __expf(sacc[nt].x) : 0.f;
            float ey = mv ? __expf(sacc[nt].y) : 0.f;
            float ez = mv ? __expf(sacc[nt].z) : 0.f;
            float ew = mv ? __expf(sacc[nt].w) : 0.f;
            rs0 += ex + ey;
            rs1 += ez + ew;
            pe[nt][0] = f2tf(ex);   // P[R0+ly  ][nt*8+2lx  ]
            pe[nt][1] = f2tf(ey);   // P[R0+ly  ][nt*8+2lx+1]
            pe[nt][2] = f2tf(ez);   // P[R0+ly+8][nt*8+2lx  ]
            pe[nt][3] = f2tf(ew);   // P[R0+ly+8][nt*8+2lx+1]
        }

        // retire P2[it] — per-warp only (rows are warp-private)
        if (it < 12) asm volatile("cp.async.wait_group 1;\n" ::: "memory");
        else         asm volatile("cp.async.wait_group 0;\n" ::: "memory");
        __syncwarp();

        // PV: dual accumulate. Patch A-frags built from pe via shuffles:
        //   p(col=K0+lx)   <- lane ly*4+(lx>>1), component lx&1
        //   p(col=K0+lx+4) <- lane ly*4+2+(lx>>1), component lx&1
#pragma unroll
        for (int kk = 0; kk < 8; kk++) {
            int K0 = kk * 8;
            unsigned s0 = __shfl_sync(FULL, pe[kk][0], srcA);
            unsigned s1 = __shfl_sync(FULL, pe[kk][1], srcA);
            unsigned p0 = hiSel ? s1 : s0;
            unsigned s2 = __shfl_sync(FULL, pe[kk][2], srcA);
            unsigned s3 = __shfl_sync(FULL, pe[kk][3], srcA);
            unsigned p1 = hiSel ? s3 : s2;
            unsigned t0 = __shfl_sync(FULL, pe[kk][0], srcB);
            unsigned t1 = __shfl_sync(FULL, pe[kk][1], srcB);
            unsigned p2 = hiSel ? t1 : t0;
            unsigned t2 = __shfl_sync(FULL, pe[kk][2], srcB);
            unsigned t3 = __shfl_sync(FULL, pe[kk][3], srcB);
            unsigned p3 = hiSel ? t3 : t2;

            unsigned c0 = S.P2[R0 + ly][K0 + lx];
            unsigned c1 = S.P2[R0 + ly + 8][K0 + lx];
            unsigned c2 = S.P2[R0 + ly][K0 + lx + 4];
            unsigned c3 = S.P2[R0 + ly + 8][K0 + lx + 4];
#pragma unroll
            for (int nt = 0; nt < 4; nt++) {
                unsigned b0 = S.Vs[cur][K0 + lx][nt * 8 + ly];
                unsigned b1 = S.Vs[cur][K0 + lx + 4][nt * 8 + ly];
                mma8(opat[nt], p0, p1, p2, p3, b0, b1);
                mma8(opos[nt], c0, c1, c2, c3, b0, b1);
            }
        }
        __syncwarp();   // this warp done reading its P2 rows

        if (it < 12) {
            // P2[it+1]: warp-private refill into own rows
#pragma unroll
            for (int l = 0; l < 8; l++) {
                int idx = lane + l * 32;
                int rr = idx >> 4, cq = (idx & 15) << 2;
                cpa16(&S.P2[R0 + rr][cq], &POSg[(size_t)(q0 + R0 + rr) * N_ + m1 + cq],
                      (q0 + R0 + rr < N_) && (m1 + cq < N_));
            }
            cpa_commit();   // FIFO: { KV[it+1], P2[it+1] }
            // retire KV[it+1], then the ONLY block barrier in the loop
            asm volatile("cp.async.wait_group 1;\n" ::: "memory");
            __syncthreads();
            // FIFO: { P2[it+1] } -> invariant holds
        }
    }

    // rowsum reduce over the quad (lanes sharing a row)
    rs0 += __shfl_xor_sync(0xffffffffu, rs0, 1);
    rs0 += __shfl_xor_sync(0xffffffffu, rs0, 2);
    rs1 += __shfl_xor_sync(0xffffffffu, rs1, 1);
    rs1 += __shfl_xor_sync(0xffffffffu, rs1, 2);
    float inv0 = (1.f - gate) / rs0;
    float inv1 = (1.f - gate) / rs1;

    // epilogue: out = (1-g)/rowsum * O_patch + g * O_pos (attn sums to 1)
    int n0r = q0 + R0 + ly;
    int n1r = n0r + 8;
#pragma unroll
    for (int nt = 0; nt < 4; nt++) {
        int d = nt * 8 + lx * 2;
        if (n0r < N_) {
            float2 o;
            o.x = opat[nt].x * inv0 + gate * opos[nt].x;
            o.y = opat[nt].y * inv0 + gate * opos[nt].y;
            *(float2*)&g_att[((size_t)b * N_ + n0r) * DIM_ + h * HD_ + d] = o;
        }
        if (n1r < N_) {
            float2 o;
            o.x = opat[nt].z * inv1 + gate * opos[nt].z;
            o.y = opat[nt].w * inv1 + gate * opos[nt].w;
            *(float2*)&g_att[((size_t)b * N_ + n1r) * DIM_ + h * HD_ + d] = o;
        }
    }
}

// ---------------------------------------------------------------------------
extern "C" void kernel_launch(void* const* d_in, const int* in_sizes, int n_in,
                              void* d_out, int out_size) {
    const float* x      = (const float*)d_in[0];
    const float* Wq     = (const float*)d_in[1];
    const float* Wk     = (const float*)d_in[2];
    const float* Wv     = (const float*)d_in[3];
    const float* W_pos  = (const float*)d_in[4];
    const float* b_pos  = (const float*)d_in[5];
    const float* W_out  = (const float*)d_in[6];
    const float* b_out  = (const float*)d_in[7];
    const float* gating = (const float*)d_in[8];
    float* out = (float*)d_out;

    cudaFuncSetAttribute(attn_kernel, cudaFuncAttributeMaxDynamicSharedMemorySize,
                         (int)sizeof(ASmem));

    pos_kernel<<<H_ * N_, 256>>>(W_pos, b_pos);

    gemm_qkv<<<dim3(3 * DIM_ / 64, ROWS_ / 64), 128>>>(x, Wq, Wk, Wv);   // (18, 98)

    attn_kernel<<<dim3(13, B_ * H_), 128, sizeof(ASmem)>>>(gating);

    gemm_out<<<dim3(DIM_ / 64, ROWS_ / 64), 128>>>(W_out, b_out, out);   // (6, 98)
}

// round 14
// speedup vs baseline: 1.0198x; 1.0198x over previous
#include <cuda_runtime.h>
#include <cstdint>

#define B_   8
#define N_   784
#define DIM_ 384
#define H_   12
#define HD_  32
#define GS_  28
#define ROWS_ (B_*N_)   // 6272
#define SCALE_ 0.28867513459481287f   // 12^-0.5

__device__ float g_q[B_*H_*N_*HD_];
__device__ float g_k[B_*H_*N_*HD_];
__device__ float g_v[B_*H_*N_*HD_];
__device__ float g_att[B_*N_*DIM_];      // attn output, fp32
__device__ float g_pos[H_*N_*N_];        // normalized positional scores (tf32 bits)

// ---------------------------------------------------------------------------
// helpers
// ---------------------------------------------------------------------------
__device__ __forceinline__ unsigned f2tf(float f) {
    unsigned r; asm("cvt.rna.tf32.f32 %0, %1;" : "=r"(r) : "f"(f)); return r;
}
__device__ __forceinline__ void mma8(float4& d,
                                     unsigned a0, unsigned a1, unsigned a2, unsigned a3,
                                     unsigned b0, unsigned b1) {
    asm volatile("mma.sync.aligned.m16n8k8.row.col.f32.tf32.tf32.f32 "
                 "{%0,%1,%2,%3}, {%4,%5,%6,%7}, {%8,%9}, {%0,%1,%2,%3};\n"
                 : "+f"(d.x), "+f"(d.y), "+f"(d.z), "+f"(d.w)
                 : "r"(a0), "r"(a1), "r"(a2), "r"(a3), "r"(b0), "r"(b1));
}
__device__ __forceinline__ void cpa16(void* s, const void* g, bool pred) {
    unsigned sa = (unsigned)__cvta_generic_to_shared(s);
    int sz = pred ? 16 : 0;
    asm volatile("cp.async.cg.shared.global [%0], [%1], 16, %2;\n"
                 :: "r"(sa), "l"(g), "r"(sz) : "memory");
}
__device__ __forceinline__ void cpa_commit() {
    asm volatile("cp.async.commit_group;\n" ::: "memory");
}

// ---------------------------------------------------------------------------
// Kernel 1: normalized positional softmax  pos[h][n][m]  (writes tf32 bits)
// ---------------------------------------------------------------------------
__global__ void pos_kernel(const float* __restrict__ W_pos,
                           const float* __restrict__ b_pos) {
    int hn = blockIdx.x;
    int h = hn / N_, n = hn - h * N_;
    int nx = n % GS_, ny = n / GS_;
    float w0 = W_pos[h*3+0], w1 = W_pos[h*3+1], w2 = W_pos[h*3+2], bp = b_pos[h];
    int t = threadIdx.x;

    float lg[4];
    float lmax = -1e30f;
#pragma unroll
    for (int i = 0; i < 4; i++) {
        int m = t + i * 256;
        if (m < N_) {
            int mx = m % GS_, my = m / GS_;
            float dx = (float)(mx - nx), dy = (float)(my - ny);
            float v = fmaf(w2, dx*dx + dy*dy, fmaf(w1, dy, fmaf(w0, dx, bp)));
            lg[i] = v;
            lmax = fmaxf(lmax, v);
        } else lg[i] = -1e30f;
    }
    __shared__ float sred[8];
    __shared__ float ssum[8];
#pragma unroll
    for (int o = 16; o > 0; o >>= 1)
        lmax = fmaxf(lmax, __shfl_xor_sync(0xffffffffu, lmax, o));
    if ((t & 31) == 0) sred[t >> 5] = lmax;
    __syncthreads();
    float bmax = fmaxf(fmaxf(fmaxf(sred[0], sred[1]), fmaxf(sred[2], sred[3])),
                       fmaxf(fmaxf(sred[4], sred[5]), fmaxf(sred[6], sred[7])));

    float e[4]; float lsum = 0.f;
#pragma unroll
    for (int i = 0; i < 4; i++) { e[i] = __expf(lg[i] - bmax); lsum += e[i]; }
#pragma unroll
    for (int o = 16; o > 0; o >>= 1)
        lsum += __shfl_xor_sync(0xffffffffu, lsum, o);
    if ((t & 31) == 0) ssum[t >> 5] = lsum;
    __syncthreads();
    float tot = ((ssum[0]+ssum[1])+(ssum[2]+ssum[3]))+((ssum[4]+ssum[5])+(ssum[6]+ssum[7]));
    float inv = 1.f / tot;

    float* outp = g_pos + (size_t)hn * N_;
#pragma unroll
    for (int i = 0; i < 4; i++) {
        int m = t + i * 256;
        if (m < N_) outp[m] = __uint_as_float(f2tf(e[i] * inv));
    }
}

// ---------------------------------------------------------------------------
// Kernel 2: fused QKV tf32 GEMM (champion config: 64x64, 128 thr, reg-prefetch)
// ---------------------------------------------------------------------------
#define GSTR 36
__global__ __launch_bounds__(128) void gemm_qkv(
    const float* __restrict__ X, const float* __restrict__ Wq,
    const float* __restrict__ Wk, const float* __restrict__ Wv)
{
    __shared__ unsigned Xs[2][64][GSTR];
    __shared__ unsigned Ws[2][64][GSTR];

    int t = threadIdx.x, w = t >> 5, lane = t & 31;
    int ly = lane >> 2, lx = lane & 3;
    int wr = w >> 1, wc = w & 1;
    int row0 = blockIdx.y * 64, col0 = blockIdx.x * 64;
    int wsel = col0 / DIM_;
    int colw = col0 - wsel * DIM_;
    const float* W = (wsel == 0) ? Wq : (wsel == 1) ? Wk : Wv;
    float* Op = (wsel == 0) ? g_q : (wsel == 1) ? g_k : g_v;
    float scale = (wsel == 0) ? SCALE_ : 1.f;

    float4 rx[4], rw[4];
#pragma unroll
    for (int l = 0; l < 4; l++) {
        int idx = t + l * 128;
        int r = idx >> 3, kq = (idx & 7) << 2;
        rx[l] = *(const float4*)&X[(size_t)(row0 + r) * DIM_ + kq];
        rw[l] = *(const float4*)&W[(size_t)(colw + r) * DIM_ + kq];
    }
#pragma unroll
    for (int l = 0; l < 4; l++) {
        int idx = t + l * 128;
        int r = idx >> 3, kq = (idx & 7) << 2;
        *(uint4*)&Xs[0][r][kq] = make_uint4(f2tf(rx[l].x), f2tf(rx[l].y), f2tf(rx[l].z), f2tf(rx[l].w));
        *(uint4*)&Ws[0][r][kq] = make_uint4(f2tf(rw[l].x), f2tf(rw[l].y), f2tf(rw[l].z), f2tf(rw[l].w));
    }
    __syncthreads();

    float4 acc[2][4];
#pragma unroll
    for (int i = 0; i < 2; i++)
#pragma unroll
        for (int j = 0; j < 4; j++) acc[i][j] = make_float4(0.f, 0.f, 0.f, 0.f);

    for (int ki = 0; ki < 12; ki++) {
        int cur = ki & 1;
        if (ki < 11) {
            int k0 = (ki + 1) * 32;
#pragma unroll
            for (int l = 0; l < 4; l++) {
                int idx = t + l * 128;
                int r = idx >> 3, kq = (idx & 7) << 2;
                rx[l] = *(const float4*)&X[(size_t)(row0 + r) * DIM_ + k0 + kq];
                rw[l] = *(const float4*)&W[(size_t)(colw + r) * DIM_ + k0 + kq];
            }
        }
#pragma unroll
        for (int kk = 0; kk < 4; kk++) {
            int K0 = kk * 8;
            unsigned a[2][4];
#pragma unroll
            for (int mi = 0; mi < 2; mi++) {
                int rb = wr * 32 + mi * 16 + ly;
                a[mi][0] = Xs[cur][rb][K0 + lx];
                a[mi][1] = Xs[cur][rb + 8][K0 + lx];
                a[mi][2] = Xs[cur][rb][K0 + lx + 4];
                a[mi][3] = Xs[cur][rb + 8][K0 + lx + 4];
            }
#pragma unroll
            for (int nt = 0; nt < 4; nt++) {
                int cb = wc * 32 + nt * 8 + ly;
                unsigned b0 = Ws[cur][cb][K0 + lx];
                unsigned b1 = Ws[cur][cb][K0 + lx + 4];
                mma8(acc[0][nt], a[0][0], a[0][1], a[0][2], a[0][3], b0, b1);
                mma8(acc[1][nt], a[1][0], a[1][1], a[1][2], a[1][3], b0, b1);
            }
        }
        if (ki < 11) {
            int nxt = (ki + 1) & 1;
#pragma unroll
            for (int l = 0; l < 4; l++) {
                int idx = t + l * 128;
                int r = idx >> 3, kq = (idx & 7) << 2;
                *(uint4*)&Xs[nxt][r][kq] = make_uint4(f2tf(rx[l].x), f2tf(rx[l].y), f2tf(rx[l].z), f2tf(rx[l].w));
                *(uint4*)&Ws[nxt][r][kq] = make_uint4(f2tf(rw[l].x), f2tf(rw[l].y), f2tf(rw[l].z), f2tf(rw[l].w));
            }
        }
        __syncthreads();
    }

    int h = (colw + wc * 32) >> 5;
#pragma unroll
    for (int mi = 0; mi < 2; mi++) {
        int row = row0 + wr * 32 + mi * 16 + ly;
#pragma unroll
        for (int nt = 0; nt < 4; nt++) {
            int d = nt * 8 + lx * 2;
            {
                int b = row / N_, n = row - b * N_;
                float2 v;
                v.x = __uint_as_float(f2tf(acc[mi][nt].x * scale));
                v.y = __uint_as_float(f2tf(acc[mi][nt].y * scale));
                *(float2*)&Op[(((size_t)(b * H_ + h)) * N_ + n) * HD_ + d] = v;
            }
            {
                int row2 = row + 8;
                int b = row2 / N_, n = row2 - b * N_;
                float2 v;
                v.x = __uint_as_float(f2tf(acc[mi][nt].z * scale));
                v.y = __uint_as_float(f2tf(acc[mi][nt].w * scale));
                *(float2*)&Op[(((size_t)(b * H_ + h)) * N_ + n) * HD_ + d] = v;
            }
        }
    }
}

// ---------------------------------------------------------------------------
// Kernel 2b: out-projection tf32 GEMM (champion config), +bias, fp32
// ---------------------------------------------------------------------------
__global__ __launch_bounds__(128) void gemm_out(
    const float* __restrict__ W, const float* __restrict__ bias,
    float* __restrict__ OUTp)
{
    __shared__ unsigned Xs[2][64][GSTR];
    __shared__ unsigned Ws[2][64][GSTR];

    int t = threadIdx.x, w = t >> 5, lane = t & 31;
    int ly = lane >> 2, lx = lane & 3;
    int wr = w >> 1, wc = w & 1;
    int row0 = blockIdx.y * 64, col0 = blockIdx.x * 64;
    const float* X = g_att;

    float4 rx[4], rw[4];
#pragma unroll
    for (int l = 0; l < 4; l++) {
        int idx = t + l * 128;
        int r = idx >> 3, kq = (idx & 7) << 2;
        rx[l] = *(const float4*)&X[(size_t)(row0 + r) * DIM_ + kq];
        rw[l] = *(const float4*)&W[(size_t)(col0 + r) * DIM_ + kq];
    }
#pragma unroll
    for (int l = 0; l < 4; l++) {
        int idx = t + l * 128;
        int r = idx >> 3, kq = (idx & 7) << 2;
        *(uint4*)&Xs[0][r][kq] = make_uint4(f2tf(rx[l].x), f2tf(rx[l].y), f2tf(rx[l].z), f2tf(rx[l].w));
        *(uint4*)&Ws[0][r][kq] = make_uint4(f2tf(rw[l].x), f2tf(rw[l].y), f2tf(rw[l].z), f2tf(rw[l].w));
    }
    __syncthreads();

    float4 acc[2][4];
#pragma unroll
    for (int i = 0; i < 2; i++)
#pragma unroll
        for (int j = 0; j < 4; j++) acc[i][j] = make_float4(0.f, 0.f, 0.f, 0.f);

    for (int ki = 0; ki < 12; ki++) {
        int cur = ki & 1;
        if (ki < 11) {
            int k0 = (ki + 1) * 32;
#pragma unroll
            for (int l = 0; l < 4; l++) {
                int idx = t + l * 128;
                int r = idx >> 3, kq = (idx & 7) << 2;
                rx[l] = *(const float4*)&X[(size_t)(row0 + r) * DIM_ + k0 + kq];
                rw[l] = *(const float4*)&W[(size_t)(col0 + r) * DIM_ + k0 + kq];
            }
        }
#pragma unroll
        for (int kk = 0; kk < 4; kk++) {
            int K0 = kk * 8;
            unsigned a[2][4];
#pragma unroll
            for (int mi = 0; mi < 2; mi++) {
                int rb = wr * 32 + mi * 16 + ly;
                a[mi][0] = Xs[cur][rb][K0 + lx];
                a[mi][1] = Xs[cur][rb + 8][K0 + lx];
                a[mi][2] = Xs[cur][rb][K0 + lx + 4];
                a[mi][3] = Xs[cur][rb + 8][K0 + lx + 4];
            }
#pragma unroll
            for (int nt = 0; nt < 4; nt++) {
                int cb = wc * 32 + nt * 8 + ly;
                unsigned b0 = Ws[cur][cb][K0 + lx];
                unsigned b1 = Ws[cur][cb][K0 + lx + 4];
                mma8(acc[0][nt], a[0][0], a[0][1], a[0][2], a[0][3], b0, b1);
                mma8(acc[1][nt], a[1][0], a[1][1], a[1][2], a[1][3], b0, b1);
            }
        }
        if (ki < 11) {
            int nxt = (ki + 1) & 1;
#pragma unroll
            for (int l = 0; l < 4; l++) {
                int idx = t + l * 128;
                int r = idx >> 3, kq = (idx & 7) << 2;
                *(uint4*)&Xs[nxt][r][kq] = make_uint4(f2tf(rx[l].x), f2tf(rx[l].y), f2tf(rx[l].z), f2tf(rx[l].w));
                *(uint4*)&Ws[nxt][r][kq] = make_uint4(f2tf(rw[l].x), f2tf(rw[l].y), f2tf(rw[l].z), f2tf(rw[l].w));
            }
        }
        __syncthreads();
    }

#pragma unroll
    for (int mi = 0; mi < 2; mi++) {
        int row = row0 + wr * 32 + mi * 16 + ly;
#pragma unroll
        for (int nt = 0; nt < 4; nt++) {
            int col = col0 + wc * 32 + nt * 8 + lx * 2;
            float b0 = bias[col], b1 = bias[col + 1];
            float2 v0; v0.x = acc[mi][nt].x + b0; v0.y = acc[mi][nt].y + b1;
            *(float2*)&OUTp[(size_t)row * DIM_ + col] = v0;
            float2 v1; v1.x = acc[mi][nt].z + b0; v1.y = acc[mi][nt].w + b1;
            *(float2*)&OUTp[(size_t)(row + 8) * DIM_ + col] = v1;
        }
    }
}

// ---------------------------------------------------------------------------
// Kernel 3: fused gated attention (round-12 champion: P1 smem, warp-private
// P2, one block barrier per iter) with the ragged tail iteration PEELED:
// it=12 has only 16 valid m-columns -> run nt<2 / kk<2 only (rest is
// multiply-by-zero). Main loop it=0..11 prefetches unconditionally.
// ---------------------------------------------------------------------------
#define QSTR 36
#define VSTR 40
#define PSTR 68
struct ASmem {
    unsigned P1[64][PSTR];       // exp scores (warp-private rows)
    unsigned P2[64][PSTR];       // pos tile (warp-private rows; Q staging at start)
    unsigned Ks[2][64][QSTR];
    unsigned Vs[2][64][VSTR];
};   // 73728 B -> 3 blocks/SM

__global__ __launch_bounds__(128) void attn_kernel(const float* __restrict__ gating) {
    extern __shared__ char sraw[];
    ASmem& S = *reinterpret_cast<ASmem*>(sraw);

    int t = threadIdx.x, w = t >> 5, lane = t & 31;
    int ly = lane >> 2, lx = lane & 3;
    int bh = blockIdx.y;
    int b = bh / H_, h = bh - b * H_;
    int q0 = blockIdx.x * 64;
    int R0 = w * 16;

    const float* Qg   = g_q + (size_t)bh * N_ * HD_;
    const float* Kg   = g_k + (size_t)bh * N_ * HD_;
    const float* Vg   = g_v + (size_t)bh * N_ * HD_;
    const float* POSg = g_pos + (size_t)h * N_ * N_;

    float gate = 1.f / (1.f + __expf(-gating[h]));

    // ---- prologue G0 (block-wide): Q staged into P2 rows + KV[0]
#pragma unroll
    for (int l = 0; l < 4; l++) {
        int idx = t + l * 128;
        int r = idx >> 3, dq = (idx & 7) << 2;
        cpa16(&S.P2[r][dq], &Qg[(size_t)(q0 + r) * HD_ + dq], q0 + r < N_);
        bool mv = r < N_;   // m0 = 0
        cpa16(&S.Ks[0][r][dq], &Kg[(size_t)r * HD_ + dq], mv);
        cpa16(&S.Vs[0][r][dq], &Vg[(size_t)r * HD_ + dq], mv);
    }
    cpa_commit();
    asm volatile("cp.async.wait_group 0;\n" ::: "memory");
    __syncthreads();

    // Q fragments -> registers (warp reads only its own rows)
    unsigned qf[4][4];
#pragma unroll
    for (int kk = 0; kk < 4; kk++) {
        int K0 = kk * 8;
        qf[kk][0] = S.P2[R0 + ly][K0 + lx];
        qf[kk][1] = S.P2[R0 + ly + 8][K0 + lx];
        qf[kk][2] = S.P2[R0 + ly][K0 + lx + 4];
        qf[kk][3] = S.P2[R0 + ly + 8][K0 + lx + 4];
    }
    __syncwarp();   // this warp done reading its Q rows; refill below is same-warp rows

    // P2[0]: warp-private refill (16 rows x 64 cols per warp, 8 float4/lane)
#pragma unroll
    for (int l = 0; l < 8; l++) {
        int idx = lane + l * 32;
        int rr = idx >> 4, cq = (idx & 15) << 2;
        cpa16(&S.P2[R0 + rr][cq], &POSg[(size_t)(q0 + R0 + rr) * N_ + cq],
              (q0 + R0 + rr < N_) && (cq < N_));
    }
    cpa_commit();   // per-thread FIFO: { P2[0] }

    float4 opat[4], opos[4];
#pragma unroll
    for (int i = 0; i < 4; i++) { opat[i] = make_float4(0.f,0.f,0.f,0.f); opos[i] = opat[i]; }
    float rs0 = 0.f, rs1 = 0.f;

    // ---- main loop: full m-tiles 0..11 (prefetch always)
    for (int it = 0; it < 12; it++) {
        int cur = it & 1;
        int nxt = (it + 1) & 1;
        int m1 = (it + 1) * 64;
        // FIFO at top: { P2[it] }
#pragma unroll
        for (int l = 0; l < 4; l++) {
            int idx = t + l * 128;
            int r = idx >> 3, dq = (idx & 7) << 2;
            bool mv = m1 + r < N_;
            cpa16(&S.Ks[nxt][r][dq], &Kg[(size_t)(m1 + r) * HD_ + dq], mv);
            cpa16(&S.Vs[nxt][r][dq], &Vg[(size_t)(m1 + r) * HD_ + dq], mv);
        }
        cpa_commit();   // FIFO: { P2[it], KV[it+1] }

        // S = Q K^T  (16 x 64 per warp)
        float4 sacc[8];
#pragma unroll
        for (int i = 0; i < 8; i++) sacc[i] = make_float4(0.f,0.f,0.f,0.f);
#pragma unroll
        for (int kk = 0; kk < 4; kk++) {
            int K0 = kk * 8;
#pragma unroll
            for (int nt = 0; nt < 8; nt++) {
                unsigned b0 = S.Ks[cur][nt * 8 + ly][K0 + lx];
                unsigned b1 = S.Ks[cur][nt * 8 + ly][K0 + lx + 4];
                mma8(sacc[nt], qf[kk][0], qf[kk][1], qf[kk][2], qf[kk][3], b0, b1);
            }
        }

        // exp + rowsum + stage P1 (warp-private rows; all columns valid)
#pragma unroll
        for (int nt = 0; nt < 8; nt++) {
            float ex = __expf(sacc[nt].x);
            float ey = __expf(sacc[nt].y);
            float ez = __expf(sacc[nt].z);
            float ew = __expf(sacc[nt].w);
            rs0 += ex + ey;
            rs1 += ez + ew;
            uint2 u01; u01.x = f2tf(ex); u01.y = f2tf(ey);
            uint2 u23; u23.x = f2tf(ez); u23.y = f2tf(ew);
            *(uint2*)&S.P1[R0 + ly][nt * 8 + lx * 2] = u01;
            *(uint2*)&S.P1[R0 + ly + 8][nt * 8 + lx * 2] = u23;
        }

        // retire P2[it] — per-warp only (rows are warp-private)
        asm volatile("cp.async.wait_group 1;\n" ::: "memory");
        __syncwarp();

        // PV: dual accumulate (16 x 32 per warp) using P1, P2 (own rows), Vs[cur]
#pragma unroll
        for (int kk = 0; kk < 8; kk++) {
            int K0 = kk * 8;
            unsigned p0 = S.P1[R0 + ly][K0 + lx];
            unsigned p1 = S.P1[R0 + ly + 8][K0 + lx];
            unsigned p2 = S.P1[R0 + ly][K0 + lx + 4];
            unsigned p3 = S.P1[R0 + ly + 8][K0 + lx + 4];
            unsigned c0 = S.P2[R0 + ly][K0 + lx];
            unsigned c1 = S.P2[R0 + ly + 8][K0 + lx];
            unsigned c2 = S.P2[R0 + ly][K0 + lx + 4];
            unsigned c3 = S.P2[R0 + ly + 8][K0 + lx + 4];
#pragma unroll
            for (int nt = 0; nt < 4; nt++) {
                unsigned b0 = S.Vs[cur][K0 + lx][nt * 8 + ly];
                unsigned b1 = S.Vs[cur][K0 + lx + 4][nt * 8 + ly];
                mma8(opat[nt], p0, p1, p2, p3, b0, b1);
                mma8(opos[nt], c0, c1, c2, c3, b0, b1);
            }
        }
        __syncwarp();   // this warp done reading its P2 rows

        // P2[it+1]: warp-private refill into own rows
#pragma unroll
        for (int l = 0; l < 8; l++) {
            int idx = lane + l * 32;
            int rr = idx >> 4, cq = (idx & 15) << 2;
            cpa16(&S.P2[R0 + rr][cq], &POSg[(size_t)(q0 + R0 + rr) * N_ + m1 + cq],
                  (q0 + R0 + rr < N_) && (m1 + cq < N_));
        }
        cpa_commit();   // FIFO: { KV[it+1], P2[it+1] }
        asm volatile("cp.async.wait_group 1;\n" ::: "memory");
        __syncthreads();   // the ONLY block barrier in the loop
        // FIFO: { P2[it+1] } -> invariant holds
    }

    // ---- peeled tail: it=12, m0=768, only 16 valid cols (nt<2 / kk<2)
    {
        int cur = 0;   // 12 & 1
        float4 sacc[2];
        sacc[0] = make_float4(0.f,0.f,0.f,0.f);
        sacc[1] = sacc[0];
#pragma unroll
        for (int kk = 0; kk < 4; kk++) {
            int K0 = kk * 8;
#pragma unroll
            for (int nt = 0; nt < 2; nt++) {
                unsigned b0 = S.Ks[cur][nt * 8 + ly][K0 + lx];
                unsigned b1 = S.Ks[cur][nt * 8 + ly][K0 + lx + 4];
                mma8(sacc[nt], qf[kk][0], qf[kk][1], qf[kk][2], qf[kk][3], b0, b1);
            }
        }
#pragma unroll
        for (int nt = 0; nt < 2; nt++) {
            float ex = __expf(sacc[nt].x);
            float ey = __expf(sacc[nt].y);
            float ez = __expf(sacc[nt].z);
            float ew = __expf(sacc[nt].w);
            rs0 += ex + ey;
            rs1 += ez + ew;
            uint2 u01; u01.x = f2tf(ex); u01.y = f2tf(ey);
            uint2 u23; u23.x = f2tf(ez); u23.y = f2tf(ew);
            *(uint2*)&S.P1[R0 + ly][nt * 8 + lx * 2] = u01;
            *(uint2*)&S.P1[R0 + ly + 8][nt * 8 + lx * 2] = u23;
        }
        // retire P2[12] (last outstanding group)
        asm volatile("cp.async.wait_group 0;\n" ::: "memory");
        __syncwarp();
#pragma unroll
        for (int kk = 0; kk < 2; kk++) {
            int K0 = kk * 8;
            unsigned p0 = S.P1[R0 + ly][K0 + lx];
            unsigned p1 = S.P1[R0 + ly + 8][K0 + lx];
            unsigned p2 = S.P1[R0 + ly][K0 + lx + 4];
            unsigned p3 = S.P1[R0 + ly + 8][K0 + lx + 4];
            unsigned c0 = S.P2[R0 + ly][K0 + lx];
            unsigned c1 = S.P2[R0 + ly + 8][K0 + lx];
            unsigned c2 = S.P2[R0 + ly][K0 + lx + 4];
            unsigned c3 = S.P2[R0 + ly + 8][K0 + lx + 4];
#pragma unroll
            for (int nt = 0; nt < 4; nt++) {
                unsigned b0 = S.Vs[cur][K0 + lx][nt * 8 + ly];
                unsigned b1 = S.Vs[cur][K0 + lx + 4][nt * 8 + ly];
                mma8(opat[nt], p0, p1, p2, p3, b0, b1);
                mma8(opos[nt], c0, c1, c2, c3, b0, b1);
            }
        }
    }

    // rowsum reduce over the quad (lanes sharing a row)
    rs0 += __shfl_xor_sync(0xffffffffu, rs0, 1);
    rs0 += __shfl_xor_sync(0xffffffffu, rs0, 2);
    rs1 += __shfl_xor_sync(0xffffffffu, rs1, 1);
    rs1 += __shfl_xor_sync(0xffffffffu, rs1, 2);
    float inv0 = (1.f - gate) / rs0;
    float inv1 = (1.f - gate) / rs1;

    // epilogue: out = (1-g)/rowsum * O_patch + g * O_pos (attn sums to 1)
    int n0r = q0 + R0 + ly;
    int n1r = n0r + 8;
#pragma unroll
    for (int nt = 0; nt < 4; nt++) {
        int d = nt * 8 + lx * 2;
        if (n0r < N_) {
            float2 o;
            o.x = opat[nt].x * inv0 + gate * opos[nt].x;
            o.y = opat[nt].y * inv0 + gate * opos[nt].y;
            *(float2*)&g_att[((size_t)b * N_ + n0r) * DIM_ + h * HD_ + d] = o;
        }
        if (n1r < N_) {
            float2 o;
            o.x = opat[nt].z * inv1 + gate * opos[nt].z;
            o.y = opat[nt].w * inv1 + gate * opos[nt].w;
            *(float2*)&g_att[((size_t)b * N_ + n1r) * DIM_ + h * HD_ + d] = o;
        }
    }
}

// ---------------------------------------------------------------------------
extern "C" void kernel_launch(void* const* d_in, const int* in_sizes, int n_in,
                              void* d_out, int out_size) {
    const float* x      = (const float*)d_in[0];
    const float* Wq     = (const float*)d_in[1];
    const float* Wk     = (const float*)d_in[2];
    const float* Wv     = (const float*)d_in[3];
    const float* W_pos  = (const float*)d_in[4];
    const float* b_pos  = (const float*)d_in[5];
    const float* W_out  = (const float*)d_in[6];
    const float* b_out  = (const float*)d_in[7];
    const float* gating = (const float*)d_in[8];
    float* out = (float*)d_out;

    cudaFuncSetAttribute(attn_kernel, cudaFuncAttributeMaxDynamicSharedMemorySize,
                         (int)sizeof(ASmem));

    pos_kernel<<<H_ * N_, 256>>>(W_pos, b_pos);

    gemm_qkv<<<dim3(3 * DIM_ / 64, ROWS_ / 64), 128>>>(x, Wq, Wk, Wv);   // (18, 98)

    attn_kernel<<<dim3(13, B_ * H_), 128, sizeof(ASmem)>>>(gating);

    gemm_out<<<dim3(DIM_ / 64, ROWS_ / 64), 128>>>(W_out, b_out, out);   // (6, 98)
}

// round 15
// speedup vs baseline: 1.0428x; 1.0225x over previous
#include <cuda_runtime.h>
#include <cstdint>

#define B_   8
#define N_   784
#define DIM_ 384
#define H_   12
#define HD_  32
#define GS_  28
#define ROWS_ (B_*N_)   // 6272
#define SCALE_ 0.28867513459481287f   // 12^-0.5

__device__ float g_q[B_*H_*N_*HD_];
__device__ float g_k[B_*H_*N_*HD_];
__device__ float g_v[B_*H_*N_*HD_];
__device__ float g_att[B_*N_*DIM_];      // attn output, fp32
__device__ float g_pos[H_*N_*N_];        // normalized positional scores (tf32 bits)

// ---------------------------------------------------------------------------
// helpers
// ---------------------------------------------------------------------------
__device__ __forceinline__ unsigned f2tf(float f) {
    unsigned r; asm("cvt.rna.tf32.f32 %0, %1;" : "=r"(r) : "f"(f)); return r;
}
__device__ __forceinline__ void mma8(float4& d,
                                     unsigned a0, unsigned a1, unsigned a2, unsigned a3,
                                     unsigned b0, unsigned b1) {
    asm volatile("mma.sync.aligned.m16n8k8.row.col.f32.tf32.tf32.f32 "
                 "{%0,%1,%2,%3}, {%4,%5,%6,%7}, {%8,%9}, {%0,%1,%2,%3};\n"
                 : "+f"(d.x), "+f"(d.y), "+f"(d.z), "+f"(d.w)
                 : "r"(a0), "r"(a1), "r"(a2), "r"(a3), "r"(b0), "r"(b1));
}
__device__ __forceinline__ void cpa16(void* s, const void* g, bool pred) {
    unsigned sa = (unsigned)__cvta_generic_to_shared(s);
    int sz = pred ? 16 : 0;
    asm volatile("cp.async.cg.shared.global [%0], [%1], 16, %2;\n"
                 :: "r"(sa), "l"(g), "r"(sz) : "memory");
}
__device__ __forceinline__ void cpa_commit() {
    asm volatile("cp.async.commit_group;\n" ::: "memory");
}
__device__ __forceinline__ uint4 ldm4(unsigned addr) {
    uint4 v;
    asm volatile("ldmatrix.sync.aligned.m8n8.x4.shared.b16 {%0,%1,%2,%3}, [%4];\n"
                 : "=r"(v.x), "=r"(v.y), "=r"(v.z), "=r"(v.w) : "r"(addr));
    return v;
}

// ---------------------------------------------------------------------------
// Kernel 1: normalized positional softmax  pos[h][n][m]  (writes tf32 bits)
// ---------------------------------------------------------------------------
__global__ void pos_kernel(const float* __restrict__ W_pos,
                           const float* __restrict__ b_pos) {
    int hn = blockIdx.x;
    int h = hn / N_, n = hn - h * N_;
    int nx = n % GS_, ny = n / GS_;
    float w0 = W_pos[h*3+0], w1 = W_pos[h*3+1], w2 = W_pos[h*3+2], bp = b_pos[h];
    int t = threadIdx.x;

    float lg[4];
    float lmax = -1e30f;
#pragma unroll
    for (int i = 0; i < 4; i++) {
        int m = t + i * 256;
        if (m < N_) {
            int mx = m % GS_, my = m / GS_;
            float dx = (float)(mx - nx), dy = (float)(my - ny);
            float v = fmaf(w2, dx*dx + dy*dy, fmaf(w1, dy, fmaf(w0, dx, bp)));
            lg[i] = v;
            lmax = fmaxf(lmax, v);
        } else lg[i] = -1e30f;
    }
    __shared__ float sred[8];
    __shared__ float ssum[8];
#pragma unroll
    for (int o = 16; o > 0; o >>= 1)
        lmax = fmaxf(lmax, __shfl_xor_sync(0xffffffffu, lmax, o));
    if ((t & 31) == 0) sred[t >> 5] = lmax;
    __syncthreads();
    float bmax = fmaxf(fmaxf(fmaxf(sred[0], sred[1]), fmaxf(sred[2], sred[3])),
                       fmaxf(fmaxf(sred[4], sred[5]), fmaxf(sred[6], sred[7])));

    float e[4]; float lsum = 0.f;
#pragma unroll
    for (int i = 0; i < 4; i++) { e[i] = __expf(lg[i] - bmax); lsum += e[i]; }
#pragma unroll
    for (int o = 16; o > 0; o >>= 1)
        lsum += __shfl_xor_sync(0xffffffffu, lsum, o);
    if ((t & 31) == 0) ssum[t >> 5] = lsum;
    __syncthreads();
    float tot = ((ssum[0]+ssum[1])+(ssum[2]+ssum[3]))+((ssum[4]+ssum[5])+(ssum[6]+ssum[7]));
    float inv = 1.f / tot;

    float* outp = g_pos + (size_t)hn * N_;
#pragma unroll
    for (int i = 0; i < 4; i++) {
        int m = t + i * 256;
        if (m < N_) outp[m] = __uint_as_float(f2tf(e[i] * inv));
    }
}

// ---------------------------------------------------------------------------
// Kernel 2: fused QKV tf32 GEMM (champion config: 64x64, 128 thr, reg-prefetch)
// ---------------------------------------------------------------------------
#define GSTR 36
__global__ __launch_bounds__(128) void gemm_qkv(
    const float* __restrict__ X, const float* __restrict__ Wq,
    const float* __restrict__ Wk, const float* __restrict__ Wv)
{
    __shared__ unsigned Xs[2][64][GSTR];
    __shared__ unsigned Ws[2][64][GSTR];

    int t = threadIdx.x, w = t >> 5, lane = t & 31;
    int ly = lane >> 2, lx = lane & 3;
    int wr = w >> 1, wc = w & 1;
    int row0 = blockIdx.y * 64, col0 = blockIdx.x * 64;
    int wsel = col0 / DIM_;
    int colw = col0 - wsel * DIM_;
    const float* W = (wsel == 0) ? Wq : (wsel == 1) ? Wk : Wv;
    float* Op = (wsel == 0) ? g_q : (wsel == 1) ? g_k : g_v;
    float scale = (wsel == 0) ? SCALE_ : 1.f;

    float4 rx[4], rw[4];
#pragma unroll
    for (int l = 0; l < 4; l++) {
        int idx = t + l * 128;
        int r = idx >> 3, kq = (idx & 7) << 2;
        rx[l] = *(const float4*)&X[(size_t)(row0 + r) * DIM_ + kq];
        rw[l] = *(const float4*)&W[(size_t)(colw + r) * DIM_ + kq];
    }
#pragma unroll
    for (int l = 0; l < 4; l++) {
        int idx = t + l * 128;
        int r = idx >> 3, kq = (idx & 7) << 2;
        *(uint4*)&Xs[0][r][kq] = make_uint4(f2tf(rx[l].x), f2tf(rx[l].y), f2tf(rx[l].z), f2tf(rx[l].w));
        *(uint4*)&Ws[0][r][kq] = make_uint4(f2tf(rw[l].x), f2tf(rw[l].y), f2tf(rw[l].z), f2tf(rw[l].w));
    }
    __syncthreads();

    float4 acc[2][4];
#pragma unroll
    for (int i = 0; i < 2; i++)
#pragma unroll
        for (int j = 0; j < 4; j++) acc[i][j] = make_float4(0.f, 0.f, 0.f, 0.f);

    for (int ki = 0; ki < 12; ki++) {
        int cur = ki & 1;
        if (ki < 11) {
            int k0 = (ki + 1) * 32;
#pragma unroll
            for (int l = 0; l < 4; l++) {
                int idx = t + l * 128;
                int r = idx >> 3, kq = (idx & 7) << 2;
                rx[l] = *(const float4*)&X[(size_t)(row0 + r) * DIM_ + k0 + kq];
                rw[l] = *(const float4*)&W[(size_t)(colw + r) * DIM_ + k0 + kq];
            }
        }
#pragma unroll
        for (int kk = 0; kk < 4; kk++) {
            int K0 = kk * 8;
            unsigned a[2][4];
#pragma unroll
            for (int mi = 0; mi < 2; mi++) {
                int rb = wr * 32 + mi * 16 + ly;
                a[mi][0] = Xs[cur][rb][K0 + lx];
                a[mi][1] = Xs[cur][rb + 8][K0 + lx];
                a[mi][2] = Xs[cur][rb][K0 + lx + 4];
                a[mi][3] = Xs[cur][rb + 8][K0 + lx + 4];
            }
#pragma unroll
            for (int nt = 0; nt < 4; nt++) {
                int cb = wc * 32 + nt * 8 + ly;
                unsigned b0 = Ws[cur][cb][K0 + lx];
                unsigned b1 = Ws[cur][cb][K0 + lx + 4];
                mma8(acc[0][nt], a[0][0], a[0][1], a[0][2], a[0][3], b0, b1);
                mma8(acc[1][nt], a[1][0], a[1][1], a[1][2], a[1][3], b0, b1);
            }
        }
        if (ki < 11) {
            int nxt = (ki + 1) & 1;
#pragma unroll
            for (int l = 0; l < 4; l++) {
                int idx = t + l * 128;
                int r = idx >> 3, kq = (idx & 7) << 2;
                *(uint4*)&Xs[nxt][r][kq] = make_uint4(f2tf(rx[l].x), f2tf(rx[l].y), f2tf(rx[l].z), f2tf(rx[l].w));
                *(uint4*)&Ws[nxt][r][kq] = make_uint4(f2tf(rw[l].x), f2tf(rw[l].y), f2tf(rw[l].z), f2tf(rw[l].w));
            }
        }
        __syncthreads();
    }

    int h = (colw + wc * 32) >> 5;
#pragma unroll
    for (int mi = 0; mi < 2; mi++) {
        int row = row0 + wr * 32 + mi * 16 + ly;
#pragma unroll
        for (int nt = 0; nt < 4; nt++) {
            int d = nt * 8 + lx * 2;
            {
                int b = row / N_, n = row - b * N_;
                float2 v;
                v.x = __uint_as_float(f2tf(acc[mi][nt].x * scale));
                v.y = __uint_as_float(f2tf(acc[mi][nt].y * scale));
                *(float2*)&Op[(((size_t)(b * H_ + h)) * N_ + n) * HD_ + d] = v;
            }
            {
                int row2 = row + 8;
                int b = row2 / N_, n = row2 - b * N_;
                float2 v;
                v.x = __uint_as_float(f2tf(acc[mi][nt].z * scale));
                v.y = __uint_as_float(f2tf(acc[mi][nt].w * scale));
                *(float2*)&Op[(((size_t)(b * H_ + h)) * N_ + n) * HD_ + d] = v;
            }
        }
    }
}

// ---------------------------------------------------------------------------
// Kernel 2b: out-projection tf32 GEMM (champion config), +bias, fp32
// ---------------------------------------------------------------------------
__global__ __launch_bounds__(128) void gemm_out(
    const float* __restrict__ W, const float* __restrict__ bias,
    float* __restrict__ OUTp)
{
    __shared__ unsigned Xs[2][64][GSTR];
    __shared__ unsigned Ws[2][64][GSTR];

    int t = threadIdx.x, w = t >> 5, lane = t & 31;
    int ly = lane >> 2, lx = lane & 3;
    int wr = w >> 1, wc = w & 1;
    int row0 = blockIdx.y * 64, col0 = blockIdx.x * 64;
    const float* X = g_att;

    float4 rx[4], rw[4];
#pragma unroll
    for (int l = 0; l < 4; l++) {
        int idx = t + l * 128;
        int r = idx >> 3, kq = (idx & 7) << 2;
        rx[l] = *(const float4*)&X[(size_t)(row0 + r) * DIM_ + kq];
        rw[l] = *(const float4*)&W[(size_t)(col0 + r) * DIM_ + kq];
    }
#pragma unroll
    for (int l = 0; l < 4; l++) {
        int idx = t + l * 128;
        int r = idx >> 3, kq = (idx & 7) << 2;
        *(uint4*)&Xs[0][r][kq] = make_uint4(f2tf(rx[l].x), f2tf(rx[l].y), f2tf(rx[l].z), f2tf(rx[l].w));
        *(uint4*)&Ws[0][r][kq] = make_uint4(f2tf(rw[l].x), f2tf(rw[l].y), f2tf(rw[l].z), f2tf(rw[l].w));
    }
    __syncthreads();

    float4 acc[2][4];
#pragma unroll
    for (int i = 0; i < 2; i++)
#pragma unroll
        for (int j = 0; j < 4; j++) acc[i][j] = make_float4(0.f, 0.f, 0.f, 0.f);

    for (int ki = 0; ki < 12; ki++) {
        int cur = ki & 1;
        if (ki < 11) {
            int k0 = (ki + 1) * 32;
#pragma unroll
            for (int l = 0; l < 4; l++) {
                int idx = t + l * 128;
                int r = idx >> 3, kq = (idx & 7) << 2;
                rx[l] = *(const float4*)&X[(size_t)(row0 + r) * DIM_ + k0 + kq];
                rw[l] = *(const float4*)&W[(size_t)(col0 + r) * DIM_ + k0 + kq];
            }
        }
#pragma unroll
        for (int kk = 0; kk < 4; kk++) {
            int K0 = kk * 8;
            unsigned a[2][4];
#pragma unroll
            for (int mi = 0; mi < 2; mi++) {
                int rb = wr * 32 + mi * 16 + ly;
                a[mi][0] = Xs[cur][rb][K0 + lx];
                a[mi][1] = Xs[cur][rb + 8][K0 + lx];
                a[mi][2] = Xs[cur][rb][K0 + lx + 4];
                a[mi][3] = Xs[cur][rb + 8][K0 + lx + 4];
            }
#pragma unroll
            for (int nt = 0; nt < 4; nt++) {
                int cb = wc * 32 + nt * 8 + ly;
                unsigned b0 = Ws[cur][cb][K0 + lx];
                unsigned b1 = Ws[cur][cb][K0 + lx + 4];
                mma8(acc[0][nt], a[0][0], a[0][1], a[0][2], a[0][3], b0, b1);
                mma8(acc[1][nt], a[1][0], a[1][1], a[1][2], a[1][3], b0, b1);
            }
        }
        if (ki < 11) {
            int nxt = (ki + 1) & 1;
#pragma unroll
            for (int l = 0; l < 4; l++) {
                int idx = t + l * 128;
                int r = idx >> 3, kq = (idx & 7) << 2;
                *(uint4*)&Xs[nxt][r][kq] = make_uint4(f2tf(rx[l].x), f2tf(rx[l].y), f2tf(rx[l].z), f2tf(rx[l].w));
                *(uint4*)&Ws[nxt][r][kq] = make_uint4(f2tf(rw[l].x), f2tf(rw[l].y), f2tf(rw[l].z), f2tf(rw[l].w));
            }
        }
        __syncthreads();
    }

#pragma unroll
    for (int mi = 0; mi < 2; mi++) {
        int row = row0 + wr * 32 + mi * 16 + ly;
#pragma unroll
        for (int nt = 0; nt < 4; nt++) {
            int col = col0 + wc * 32 + nt * 8 + lx * 2;
            float b0 = bias[col], b1 = bias[col + 1];
            float2 v0; v0.x = acc[mi][nt].x + b0; v0.y = acc[mi][nt].y + b1;
            *(float2*)&OUTp[(size_t)row * DIM_ + col] = v0;
            float2 v1; v1.x = acc[mi][nt].z + b0; v1.y = acc[mi][nt].w + b1;
            *(float2*)&OUTp[(size_t)(row + 8) * DIM_ + col] = v1;
        }
    }
}

// ---------------------------------------------------------------------------
// Kernel 3: fused gated attention (round-14 champion) with ldmatrix for
// Ks B-frags and P1/P2 A-frags (same values, same mma order; ~96 fewer
// issue slots per warp-iter). V loads stay scalar LDS.
// ---------------------------------------------------------------------------
#define QSTR 36
#define VSTR 40
#define PSTR 68
struct ASmem {
    unsigned P1[64][PSTR];       // exp scores (warp-private rows)
    unsigned P2[64][PSTR];       // pos tile (warp-private rows; Q staging at start)
    unsigned Ks[2][64][QSTR];
    unsigned Vs[2][64][VSTR];
};   // 73728 B -> 3 blocks/SM

__global__ __launch_bounds__(128) void attn_kernel(const float* __restrict__ gating) {
    extern __shared__ char sraw[];
    ASmem& S = *reinterpret_cast<ASmem*>(sraw);

    int t = threadIdx.x, w = t >> 5, lane = t & 31;
    int ly = lane >> 2, lx = lane & 3;
    int bh = blockIdx.y;
    int b = bh / H_, h = bh - b * H_;
    int q0 = blockIdx.x * 64;
    int R0 = w * 16;

    // ldmatrix lane addressing
    int g8 = lane >> 3, l7 = lane & 7;
    // A-frag (P1/P2): matrices [rows0-7,c0-3],[rows8-15,c0-3],[rows0-7,c4-7],[rows8-15,c4-7]
    unsigned aoff = (unsigned)((R0 + (g8 & 1) * 8 + l7) * PSTR + (g8 >> 1) * 4) << 2;
    // B-frag (Ks): per ntpair, matrices [nt,c0-3],[nt,c4-7],[nt+1,c0-3],[nt+1,c4-7]
    unsigned brow = (unsigned)((g8 >> 1) * 8 + l7);
    unsigned bcol = (unsigned)((g8 & 1) * 4);
    unsigned p1base = (unsigned)__cvta_generic_to_shared(&S.P1[0][0]) + aoff;
    unsigned p2base = (unsigned)__cvta_generic_to_shared(&S.P2[0][0]) + aoff;
    unsigned ksb0   = (unsigned)__cvta_generic_to_shared(&S.Ks[0][0][0]);

    const float* Qg   = g_q + (size_t)bh * N_ * HD_;
    const float* Kg   = g_k + (size_t)bh * N_ * HD_;
    const float* Vg   = g_v + (size_t)bh * N_ * HD_;
    const float* POSg = g_pos + (size_t)h * N_ * N_;

    float gate = 1.f / (1.f + __expf(-gating[h]));

    // ---- prologue G0 (block-wide): Q staged into P2 rows + KV[0]
#pragma unroll
    for (int l = 0; l < 4; l++) {
        int idx = t + l * 128;
        int r = idx >> 3, dq = (idx & 7) << 2;
        cpa16(&S.P2[r][dq], &Qg[(size_t)(q0 + r) * HD_ + dq], q0 + r < N_);
        bool mv = r < N_;   // m0 = 0
        cpa16(&S.Ks[0][r][dq], &Kg[(size_t)r * HD_ + dq], mv);
        cpa16(&S.Vs[0][r][dq], &Vg[(size_t)r * HD_ + dq], mv);
    }
    cpa_commit();
    asm volatile("cp.async.wait_group 0;\n" ::: "memory");
    __syncthreads();

    // Q fragments -> registers (warp reads only its own rows)
    unsigned qf[4][4];
#pragma unroll
    for (int kk = 0; kk < 4; kk++) {
        int K0 = kk * 8;
        qf[kk][0] = S.P2[R0 + ly][K0 + lx];
        qf[kk][1] = S.P2[R0 + ly + 8][K0 + lx];
        qf[kk][2] = S.P2[R0 + ly][K0 + lx + 4];
        qf[kk][3] = S.P2[R0 + ly + 8][K0 + lx + 4];
    }
    __syncwarp();

    // P2[0]: warp-private refill (16 rows x 64 cols per warp, 8 float4/lane)
#pragma unroll
    for (int l = 0; l < 8; l++) {
        int idx = lane + l * 32;
        int rr = idx >> 4, cq = (idx & 15) << 2;
        cpa16(&S.P2[R0 + rr][cq], &POSg[(size_t)(q0 + R0 + rr) * N_ + cq],
              (q0 + R0 + rr < N_) && (cq < N_));
    }
    cpa_commit();   // per-thread FIFO: { P2[0] }

    float4 opat[4], opos[4];
#pragma unroll
    for (int i = 0; i < 4; i++) { opat[i] = make_float4(0.f,0.f,0.f,0.f); opos[i] = opat[i]; }
    float rs0 = 0.f, rs1 = 0.f;

    // ---- main loop: full m-tiles 0..11 (prefetch always)
    for (int it = 0; it < 12; it++) {
        int cur = it & 1;
        int nxt = (it + 1) & 1;
        int m1 = (it + 1) * 64;
        unsigned ksc = ksb0 + (unsigned)(cur * 64 * QSTR) * 4u;
#pragma unroll
        for (int l = 0; l < 4; l++) {
            int idx = t + l * 128;
            int r = idx >> 3, dq = (idx & 7) << 2;
            bool mv = m1 + r < N_;
            cpa16(&S.Ks[nxt][r][dq], &Kg[(size_t)(m1 + r) * HD_ + dq], mv);
            cpa16(&S.Vs[nxt][r][dq], &Vg[(size_t)(m1 + r) * HD_ + dq], mv);
        }
        cpa_commit();   // FIFO: { P2[it], KV[it+1] }

        // S = Q K^T  (16 x 64 per warp), B-frags via ldmatrix
        float4 sacc[8];
#pragma unroll
        for (int i = 0; i < 8; i++) sacc[i] = make_float4(0.f,0.f,0.f,0.f);
#pragma unroll
        for (int kk = 0; kk < 4; kk++) {
            int K0 = kk * 8;
#pragma unroll
            for (int ntp = 0; ntp < 4; ntp++) {
                unsigned addr = ksc + (((ntp * 16 + brow) * QSTR + bcol + K0) << 2);
                uint4 bb = ldm4(addr);
                mma8(sacc[ntp*2],   qf[kk][0], qf[kk][1], qf[kk][2], qf[kk][3], bb.x, bb.y);
                mma8(sacc[ntp*2+1], qf[kk][0], qf[kk][1], qf[kk][2], qf[kk][3], bb.z, bb.w);
            }
        }

        // exp + rowsum + stage P1 (warp-private rows; all columns valid)
#pragma unroll
        for (int nt = 0; nt < 8; nt++) {
            float ex = __expf(sacc[nt].x);
            float ey = __expf(sacc[nt].y);
            float ez = __expf(sacc[nt].z);
            float ew = __expf(sacc[nt].w);
            rs0 += ex + ey;
            rs1 += ez + ew;
            uint2 u01; u01.x = f2tf(ex); u01.y = f2tf(ey);
            uint2 u23; u23.x = f2tf(ez); u23.y = f2tf(ew);
            *(uint2*)&S.P1[R0 + ly][nt * 8 + lx * 2] = u01;
            *(uint2*)&S.P1[R0 + ly + 8][nt * 8 + lx * 2] = u23;
        }

        // retire P2[it] — per-warp only
        asm volatile("cp.async.wait_group 1;\n" ::: "memory");
        __syncwarp();

        // PV: dual accumulate, A-frags via ldmatrix (P1, P2), V scalar
#pragma unroll
        for (int kk = 0; kk < 8; kk++) {
            int K0 = kk * 8;
            uint4 P = ldm4(p1base + ((unsigned)K0 << 2));
            uint4 C = ldm4(p2base + ((unsigned)K0 << 2));
#pragma unroll
            for (int nt = 0; nt < 4; nt++) {
                unsigned b0 = S.Vs[cur][K0 + lx][nt * 8 + ly];
                unsigned b1 = S.Vs[cur][K0 + lx + 4][nt * 8 + ly];
                mma8(opat[nt], P.x, P.y, P.z, P.w, b0, b1);
                mma8(opos[nt], C.x, C.y, C.z, C.w, b0, b1);
            }
        }
        __syncwarp();   // this warp done reading its P2 rows

        // P2[it+1]: warp-private refill into own rows
#pragma unroll
        for (int l = 0; l < 8; l++) {
            int idx = lane + l * 32;
            int rr = idx >> 4, cq = (idx & 15) << 2;
            cpa16(&S.P2[R0 + rr][cq], &POSg[(size_t)(q0 + R0 + rr) * N_ + m1 + cq],
                  (q0 + R0 + rr < N_) && (m1 + cq < N_));
        }
        cpa_commit();   // FIFO: { KV[it+1], P2[it+1] }
        asm volatile("cp.async.wait_group 1;\n" ::: "memory");
        __syncthreads();   // the ONLY block barrier in the loop
    }

    // ---- peeled tail: it=12, m0=768, only 16 valid cols (ntp=0 / kk<2)
    {
        unsigned ksc = ksb0;   // cur = 0
        float4 sacc[2];
        sacc[0] = make_float4(0.f,0.f,0.f,0.f);
        sacc[1] = sacc[0];
#pragma unroll
        for (int kk = 0; kk < 4; kk++) {
            int K0 = kk * 8;
            unsigned addr = ksc + (((brow) * QSTR + bcol + K0) << 2);
            uint4 bb = ldm4(addr);
            mma8(sacc[0], qf[kk][0], qf[kk][1], qf[kk][2], qf[kk][3], bb.x, bb.y);
            mma8(sacc[1], qf[kk][0], qf[kk][1], qf[kk][2], qf[kk][3], bb.z, bb.w);
        }
#pragma unroll
        for (int nt = 0; nt < 2; nt++) {
            float ex = __expf(sacc[nt].x);
            float ey = __expf(sacc[nt].y);
            float ez = __expf(sacc[nt].z);
            float ew = __expf(sacc[nt].w);
            rs0 += ex + ey;
            rs1 += ez + ew;
            uint2 u01; u01.x = f2tf(ex); u01.y = f2tf(ey);
            uint2 u23; u23.x = f2tf(ez); u23.y = f2tf(ew);
            *(uint2*)&S.P1[R0 + ly][nt * 8 + lx * 2] = u01;
            *(uint2*)&S.P1[R0 + ly + 8][nt * 8 + lx * 2] = u23;
        }
        asm volatile("cp.async.wait_group 0;\n" ::: "memory");
        __syncwarp();
#pragma unroll
        for (int kk = 0; kk < 2; kk++) {
            int K0 = kk * 8;
            uint4 P = ldm4(p1base + ((unsigned)K0 << 2));
            uint4 C = ldm4(p2base + ((unsigned)K0 << 2));
#pragma unroll
            for (int nt = 0; nt < 4; nt++) {
                unsigned b0 = S.Vs[0][K0 + lx][nt * 8 + ly];
                unsigned b1 = S.Vs[0][K0 + lx + 4][nt * 8 + ly];
                mma8(opat[nt], P.x, P.y, P.z, P.w, b0, b1);
                mma8(opos[nt], C.x, C.y, C.z, C.w, b0, b1);
            }
        }
    }

    // rowsum reduce over the quad (lanes sharing a row)
    rs0 += __shfl_xor_sync(0xffffffffu, rs0, 1);
    rs0 += __shfl_xor_sync(0xffffffffu, rs0, 2);
    rs1 += __shfl_xor_sync(0xffffffffu, rs1, 1);
    rs1 += __shfl_xor_sync(0xffffffffu, rs1, 2);
    float inv0 = (1.f - gate) / rs0;
    float inv1 = (1.f - gate) / rs1;

    // epilogue: out = (1-g)/rowsum * O_patch + g * O_pos (attn sums to 1)
    int n0r = q0 + R0 + ly;
    int n1r = n0r + 8;
#pragma unroll
    for (int nt = 0; nt < 4; nt++) {
        int d = nt * 8 + lx * 2;
        if (n0r < N_) {
            float2 o;
            o.x = opat[nt].x * inv0 + gate * opos[nt].x;
            o.y = opat[nt].y * inv0 + gate * opos[nt].y;
            *(float2*)&g_att[((size_t)b * N_ + n0r) * DIM_ + h * HD_ + d] = o;
        }
        if (n1r < N_) {
            float2 o;
            o.x = opat[nt].z * inv1 + gate * opos[nt].z;
            o.y = opat[nt].w * inv1 + gate * opos[nt].w;
            *(float2*)&g_att[((size_t)b * N_ + n1r) * DIM_ + h * HD_ + d] = o;
        }
    }
}

// ---------------------------------------------------------------------------
extern "C" void kernel_launch(void* const* d_in, const int* in_sizes, int n_in,
                              void* d_out, int out_size) {
    const float* x      = (const float*)d_in[0];
    const float* Wq     = (const float*)d_in[1];
    const float* Wk     = (const float*)d_in[2];
    const float* Wv     = (const float*)d_in[3];
    const float* W_pos  = (const float*)d_in[4];
    const float* b_pos  = (const float*)d_in[5];
    const float* W_out  = (const float*)d_in[6];
    const float* b_out  = (const float*)d_in[7];
    const float* gating = (const float*)d_in[8];
    float* out = (float*)d_out;

    cudaFuncSetAttribute(attn_kernel, cudaFuncAttributeMaxDynamicSharedMemorySize,
                         (int)sizeof(ASmem));

    pos_kernel<<<H_ * N_, 256>>>(W_pos, b_pos);

    gemm_qkv<<<dim3(3 * DIM_ / 64, ROWS_ / 64), 128>>>(x, Wq, Wk, Wv);   // (18, 98)

    attn_kernel<<<dim3(13, B_ * H_), 128, sizeof(ASmem)>>>(gating);

    gemm_out<<<dim3(DIM_ / 64, ROWS_ / 64), 128>>>(W_out, b_out, out);   // (6, 98)
}

// round 16
// speedup vs baseline: 1.0801x; 1.0358x over previous
#include <cuda_runtime.h>
#include <cstdint>

#define B_   8
#define N_   784
#define DIM_ 384
#define H_   12
#define HD_  32
#define GS_  28
#define ROWS_ (B_*N_)   // 6272
#define SCALE_ 0.28867513459481287f   // 12^-0.5

__device__ float g_q[B_*H_*N_*HD_];
__device__ float g_k[B_*H_*N_*HD_];
__device__ float g_v[B_*H_*N_*HD_];
__device__ float g_att[B_*N_*DIM_];      // attn output, fp32
__device__ float g_pos[H_*N_*N_];        // normalized positional scores (tf32 bits)

// ---------------------------------------------------------------------------
// helpers
// ---------------------------------------------------------------------------
__device__ __forceinline__ unsigned f2tf(float f) {
    unsigned r; asm("cvt.rna.tf32.f32 %0, %1;" : "=r"(r) : "f"(f)); return r;
}
__device__ __forceinline__ void mma8(float4& d,
                                     unsigned a0, unsigned a1, unsigned a2, unsigned a3,
                                     unsigned b0, unsigned b1) {
    asm volatile("mma.sync.aligned.m16n8k8.row.col.f32.tf32.tf32.f32 "
                 "{%0,%1,%2,%3}, {%4,%5,%6,%7}, {%8,%9}, {%0,%1,%2,%3};\n"
                 : "+f"(d.x), "+f"(d.y), "+f"(d.z), "+f"(d.w)
                 : "r"(a0), "r"(a1), "r"(a2), "r"(a3), "r"(b0), "r"(b1));
}
__device__ __forceinline__ void cpa16(void* s, const void* g, bool pred) {
    unsigned sa = (unsigned)__cvta_generic_to_shared(s);
    int sz = pred ? 16 : 0;
    asm volatile("cp.async.cg.shared.global [%0], [%1], 16, %2;\n"
                 :: "r"(sa), "l"(g), "r"(sz) : "memory");
}
__device__ __forceinline__ void cpa_commit() {
    asm volatile("cp.async.commit_group;\n" ::: "memory");
}
__device__ __forceinline__ uint4 ldm4(unsigned addr) {
    uint4 v;
    asm volatile("ldmatrix.sync.aligned.m8n8.x4.shared.b16 {%0,%1,%2,%3}, [%4];\n"
                 : "=r"(v.x), "=r"(v.y), "=r"(v.z), "=r"(v.w) : "r"(addr));
    return v;
}

// ---------------------------------------------------------------------------
// Kernel 1: normalized positional softmax  pos[h][n][m]  (writes tf32 bits)
// ---------------------------------------------------------------------------
__global__ void pos_kernel(const float* __restrict__ W_pos,
                           const float* __restrict__ b_pos) {
    int hn = blockIdx.x;
    int h = hn / N_, n = hn - h * N_;
    int nx = n % GS_, ny = n / GS_;
    float w0 = W_pos[h*3+0], w1 = W_pos[h*3+1], w2 = W_pos[h*3+2], bp = b_pos[h];
    int t = threadIdx.x;

    float lg[4];
    float lmax = -1e30f;
#pragma unroll
    for (int i = 0; i < 4; i++) {
        int m = t + i * 256;
        if (m < N_) {
            int mx = m % GS_, my = m / GS_;
            float dx = (float)(mx - nx), dy = (float)(my - ny);
            float v = fmaf(w2, dx*dx + dy*dy, fmaf(w1, dy, fmaf(w0, dx, bp)));
            lg[i] = v;
            lmax = fmaxf(lmax, v);
        } else lg[i] = -1e30f;
    }
    __shared__ float sred[8];
    __shared__ float ssum[8];
#pragma unroll
    for (int o = 16; o > 0; o >>= 1)
        lmax = fmaxf(lmax, __shfl_xor_sync(0xffffffffu, lmax, o));
    if ((t & 31) == 0) sred[t >> 5] = lmax;
    __syncthreads();
    float bmax = fmaxf(fmaxf(fmaxf(sred[0], sred[1]), fmaxf(sred[2], sred[3])),
                       fmaxf(fmaxf(sred[4], sred[5]), fmaxf(sred[6], sred[7])));

    float e[4]; float lsum = 0.f;
#pragma unroll
    for (int i = 0; i < 4; i++) { e[i] = __expf(lg[i] - bmax); lsum += e[i]; }
#pragma unroll
    for (int o = 16; o > 0; o >>= 1)
        lsum += __shfl_xor_sync(0xffffffffu, lsum, o);
    if ((t & 31) == 0) ssum[t >> 5] = lsum;
    __syncthreads();
    float tot = ((ssum[0]+ssum[1])+(ssum[2]+ssum[3]))+((ssum[4]+ssum[5])+(ssum[6]+ssum[7]));
    float inv = 1.f / tot;

    float* outp = g_pos + (size_t)hn * N_;
#pragma unroll
    for (int i = 0; i < 4; i++) {
        int m = t + i * 256;
        if (m < N_) outp[m] = __uint_as_float(f2tf(e[i] * inv));
    }
}

// ---------------------------------------------------------------------------
// Kernel 2: fused QKV tf32 GEMM (champion config + ldmatrix fragment loads)
// ---------------------------------------------------------------------------
#define GSTR 36
__global__ __launch_bounds__(128) void gemm_qkv(
    const float* __restrict__ X, const float* __restrict__ Wq,
    const float* __restrict__ Wk, const float* __restrict__ Wv)
{
    __shared__ unsigned Xs[2][64][GSTR];
    __shared__ unsigned Ws[2][64][GSTR];

    int t = threadIdx.x, w = t >> 5, lane = t & 31;
    int ly = lane >> 2, lx = lane & 3;
    int wr = w >> 1, wc = w & 1;
    int row0 = blockIdx.y * 64, col0 = blockIdx.x * 64;
    int wsel = col0 / DIM_;
    int colw = col0 - wsel * DIM_;
    const float* W = (wsel == 0) ? Wq : (wsel == 1) ? Wk : Wv;
    float* Op = (wsel == 0) ? g_q : (wsel == 1) ? g_k : g_v;
    float scale = (wsel == 0) ? SCALE_ : 1.f;

    // ldmatrix lane addressing (same scheme as attn kernel, stride GSTR)
    int g8 = lane >> 3, l7 = lane & 7;
    unsigned arow = (unsigned)(wr * 32 + (g8 & 1) * 8 + l7);     // + mi*16
    unsigned acol = (unsigned)((g8 >> 1) * 4);                   // + K0
    unsigned brow = (unsigned)(wc * 32 + (g8 >> 1) * 8 + l7);    // + ntp*16
    unsigned bcol = (unsigned)((g8 & 1) * 4);                    // + K0
    unsigned xsb = (unsigned)__cvta_generic_to_shared(&Xs[0][0][0]);
    unsigned wsb = (unsigned)__cvta_generic_to_shared(&Ws[0][0][0]);
    const unsigned BUF = 64u * GSTR * 4u;

    float4 rx[4], rw[4];
#pragma unroll
    for (int l = 0; l < 4; l++) {
        int idx = t + l * 128;
        int r = idx >> 3, kq = (idx & 7) << 2;
        rx[l] = *(const float4*)&X[(size_t)(row0 + r) * DIM_ + kq];
        rw[l] = *(const float4*)&W[(size_t)(colw + r) * DIM_ + kq];
    }
#pragma unroll
    for (int l = 0; l < 4; l++) {
        int idx = t + l * 128;
        int r = idx >> 3, kq = (idx & 7) << 2;
        *(uint4*)&Xs[0][r][kq] = make_uint4(f2tf(rx[l].x), f2tf(rx[l].y), f2tf(rx[l].z), f2tf(rx[l].w));
        *(uint4*)&Ws[0][r][kq] = make_uint4(f2tf(rw[l].x), f2tf(rw[l].y), f2tf(rw[l].z), f2tf(rw[l].w));
    }
    __syncthreads();

    float4 acc[2][4];
#pragma unroll
    for (int i = 0; i < 2; i++)
#pragma unroll
        for (int j = 0; j < 4; j++) acc[i][j] = make_float4(0.f, 0.f, 0.f, 0.f);

    for (int ki = 0; ki < 12; ki++) {
        int cur = ki & 1;
        unsigned xsc = xsb + cur * BUF;
        unsigned wsc = wsb + cur * BUF;
        if (ki < 11) {
            int k0 = (ki + 1) * 32;
#pragma unroll
            for (int l = 0; l < 4; l++) {
                int idx = t + l * 128;
                int r = idx >> 3, kq = (idx & 7) << 2;
                rx[l] = *(const float4*)&X[(size_t)(row0 + r) * DIM_ + k0 + kq];
                rw[l] = *(const float4*)&W[(size_t)(colw + r) * DIM_ + k0 + kq];
            }
        }
#pragma unroll
        for (int kk = 0; kk < 4; kk++) {
            int K0 = kk * 8;
            uint4 A0 = ldm4(xsc + (((arow) * GSTR + acol + K0) << 2));
            uint4 A1 = ldm4(xsc + (((arow + 16) * GSTR + acol + K0) << 2));
#pragma unroll
            for (int ntp = 0; ntp < 2; ntp++) {
                uint4 BB = ldm4(wsc + (((brow + ntp * 16) * GSTR + bcol + K0) << 2));
                mma8(acc[0][ntp*2],   A0.x, A0.y, A0.z, A0.w, BB.x, BB.y);
                mma8(acc[1][ntp*2],   A1.x, A1.y, A1.z, A1.w, BB.x, BB.y);
                mma8(acc[0][ntp*2+1], A0.x, A0.y, A0.z, A0.w, BB.z, BB.w);
                mma8(acc[1][ntp*2+1], A1.x, A1.y, A1.z, A1.w, BB.z, BB.w);
            }
        }
        if (ki < 11) {
            int nxt = (ki + 1) & 1;
#pragma unroll
            for (int l = 0; l < 4; l++) {
                int idx = t + l * 128;
                int r = idx >> 3, kq = (idx & 7) << 2;
                *(uint4*)&Xs[nxt][r][kq] = make_uint4(f2tf(rx[l].x), f2tf(rx[l].y), f2tf(rx[l].z), f2tf(rx[l].w));
                *(uint4*)&Ws[nxt][r][kq] = make_uint4(f2tf(rw[l].x), f2tf(rw[l].y), f2tf(rw[l].z), f2tf(rw[l].w));
            }
        }
        __syncthreads();
    }

    int h = (colw + wc * 32) >> 5;
#pragma unroll
    for (int mi = 0; mi < 2; mi++) {
        int row = row0 + wr * 32 + mi * 16 + ly;
#pragma unroll
        for (int nt = 0; nt < 4; nt++) {
            int d = nt * 8 + lx * 2;
            {
                int b = row / N_, n = row - b * N_;
                float2 v;
                v.x = __uint_as_float(f2tf(acc[mi][nt].x * scale));
                v.y = __uint_as_float(f2tf(acc[mi][nt].y * scale));
                *(float2*)&Op[(((size_t)(b * H_ + h)) * N_ + n) * HD_ + d] = v;
            }
            {
                int row2 = row + 8;
                int b = row2 / N_, n = row2 - b * N_;
                float2 v;
                v.x = __uint_as_float(f2tf(acc[mi][nt].z * scale));
                v.y = __uint_as_float(f2tf(acc[mi][nt].w * scale));
                *(float2*)&Op[(((size_t)(b * H_ + h)) * N_ + n) * HD_ + d] = v;
            }
        }
    }
}

// ---------------------------------------------------------------------------
// Kernel 2b: out-projection tf32 GEMM (champion config + ldmatrix), +bias
// ---------------------------------------------------------------------------
__global__ __launch_bounds__(128) void gemm_out(
    const float* __restrict__ W, const float* __restrict__ bias,
    float* __restrict__ OUTp)
{
    __shared__ unsigned Xs[2][64][GSTR];
    __shared__ unsigned Ws[2][64][GSTR];

    int t = threadIdx.x, w = t >> 5, lane = t & 31;
    int ly = lane >> 2, lx = lane & 3;
    int wr = w >> 1, wc = w & 1;
    int row0 = blockIdx.y * 64, col0 = blockIdx.x * 64;
    const float* X = g_att;

    int g8 = lane >> 3, l7 = lane & 7;
    unsigned arow = (unsigned)(wr * 32 + (g8 & 1) * 8 + l7);
    unsigned acol = (unsigned)((g8 >> 1) * 4);
    unsigned brow = (unsigned)(wc * 32 + (g8 >> 1) * 8 + l7);
    unsigned bcol = (unsigned)((g8 & 1) * 4);
    unsigned xsb = (unsigned)__cvta_generic_to_shared(&Xs[0][0][0]);
    unsigned wsb = (unsigned)__cvta_generic_to_shared(&Ws[0][0][0]);
    const unsigned BUF = 64u * GSTR * 4u;

    float4 rx[4], rw[4];
#pragma unroll
    for (int l = 0; l < 4; l++) {
        int idx = t + l * 128;
        int r = idx >> 3, kq = (idx & 7) << 2;
        rx[l] = *(const float4*)&X[(size_t)(row0 + r) * DIM_ + kq];
        rw[l] = *(const float4*)&W[(size_t)(col0 + r) * DIM_ + kq];
    }
#pragma unroll
    for (int l = 0; l < 4; l++) {
        int idx = t + l * 128;
        int r = idx >> 3, kq = (idx & 7) << 2;
        *(uint4*)&Xs[0][r][kq] = make_uint4(f2tf(rx[l].x), f2tf(rx[l].y), f2tf(rx[l].z), f2tf(rx[l].w));
        *(uint4*)&Ws[0][r][kq] = make_uint4(f2tf(rw[l].x), f2tf(rw[l].y), f2tf(rw[l].z), f2tf(rw[l].w));
    }
    __syncthreads();

    float4 acc[2][4];
#pragma unroll
    for (int i = 0; i < 2; i++)
#pragma unroll
        for (int j = 0; j < 4; j++) acc[i][j] = make_float4(0.f, 0.f, 0.f, 0.f);

    for (int ki = 0; ki < 12; ki++) {
        int cur = ki & 1;
        unsigned xsc = xsb + cur * BUF;
        unsigned wsc = wsb + cur * BUF;
        if (ki < 11) {
            int k0 = (ki + 1) * 32;
#pragma unroll
            for (int l = 0; l < 4; l++) {
                int idx = t + l * 128;
                int r = idx >> 3, kq = (idx & 7) << 2;
                rx[l] = *(const float4*)&X[(size_t)(row0 + r) * DIM_ + k0 + kq];
                rw[l] = *(const float4*)&W[(size_t)(col0 + r) * DIM_ + k0 + kq];
            }
        }
#pragma unroll
        for (int kk = 0; kk < 4; kk++) {
            int K0 = kk * 8;
            uint4 A0 = ldm4(xsc + (((arow) * GSTR + acol + K0) << 2));
            uint4 A1 = ldm4(xsc + (((arow + 16) * GSTR + acol + K0) << 2));
#pragma unroll
            for (int ntp = 0; ntp < 2; ntp++) {
                uint4 BB = ldm4(wsc + (((brow + ntp * 16) * GSTR + bcol + K0) << 2));
                mma8(acc[0][ntp*2],   A0.x, A0.y, A0.z, A0.w, BB.x, BB.y);
                mma8(acc[1][ntp*2],   A1.x, A1.y, A1.z, A1.w, BB.x, BB.y);
                mma8(acc[0][ntp*2+1], A0.x, A0.y, A0.z, A0.w, BB.z, BB.w);
                mma8(acc[1][ntp*2+1], A1.x, A1.y, A1.z, A1.w, BB.z, BB.w);
            }
        }
        if (ki < 11) {
            int nxt = (ki + 1) & 1;
#pragma unroll
            for (int l = 0; l < 4; l++) {
                int idx = t + l * 128;
                int r = idx >> 3, kq = (idx & 7) << 2;
                *(uint4*)&Xs[nxt][r][kq] = make_uint4(f2tf(rx[l].x), f2tf(rx[l].y), f2tf(rx[l].z), f2tf(rx[l].w));
                *(uint4*)&Ws[nxt][r][kq] = make_uint4(f2tf(rw[l].x), f2tf(rw[l].y), f2tf(rw[l].z), f2tf(rw[l].w));
            }
        }
        __syncthreads();
    }

#pragma unroll
    for (int mi = 0; mi < 2; mi++) {
        int row = row0 + wr * 32 + mi * 16 + ly;
#pragma unroll
        for (int nt = 0; nt < 4; nt++) {
            int col = col0 + wc * 32 + nt * 8 + lx * 2;
            float b0 = bias[col], b1 = bias[col + 1];
            float2 v0; v0.x = acc[mi][nt].x + b0; v0.y = acc[mi][nt].y + b1;
            *(float2*)&OUTp[(size_t)row * DIM_ + col] = v0;
            float2 v1; v1.x = acc[mi][nt].z + b0; v1.y = acc[mi][nt].w + b1;
            *(float2*)&OUTp[(size_t)(row + 8) * DIM_ + col] = v1;
        }
    }
}

// ---------------------------------------------------------------------------
// Kernel 3: fused gated attention (round-15 champion, verbatim)
// ---------------------------------------------------------------------------
#define QSTR 36
#define VSTR 40
#define PSTR 68
struct ASmem {
    unsigned P1[64][PSTR];
    unsigned P2[64][PSTR];
    unsigned Ks[2][64][QSTR];
    unsigned Vs[2][64][VSTR];
};   // 73728 B -> 3 blocks/SM

__global__ __launch_bounds__(128) void attn_kernel(const float* __restrict__ gating) {
    extern __shared__ char sraw[];
    ASmem& S = *reinterpret_cast<ASmem*>(sraw);

    int t = threadIdx.x, w = t >> 5, lane = t & 31;
    int ly = lane >> 2, lx = lane & 3;
    int bh = blockIdx.y;
    int b = bh / H_, h = bh - b * H_;
    int q0 = blockIdx.x * 64;
    int R0 = w * 16;

    int g8 = lane >> 3, l7 = lane & 7;
    unsigned aoff = (unsigned)((R0 + (g8 & 1) * 8 + l7) * PSTR + (g8 >> 1) * 4) << 2;
    unsigned brow = (unsigned)((g8 >> 1) * 8 + l7);
    unsigned bcol = (unsigned)((g8 & 1) * 4);
    unsigned p1base = (unsigned)__cvta_generic_to_shared(&S.P1[0][0]) + aoff;
    unsigned p2base = (unsigned)__cvta_generic_to_shared(&S.P2[0][0]) + aoff;
    unsigned ksb0   = (unsigned)__cvta_generic_to_shared(&S.Ks[0][0][0]);

    const float* Qg   = g_q + (size_t)bh * N_ * HD_;
    const float* Kg   = g_k + (size_t)bh * N_ * HD_;
    const float* Vg   = g_v + (size_t)bh * N_ * HD_;
    const float* POSg = g_pos + (size_t)h * N_ * N_;

    float gate = 1.f / (1.f + __expf(-gating[h]));

#pragma unroll
    for (int l = 0; l < 4; l++) {
        int idx = t + l * 128;
        int r = idx >> 3, dq = (idx & 7) << 2;
        cpa16(&S.P2[r][dq], &Qg[(size_t)(q0 + r) * HD_ + dq], q0 + r < N_);
        bool mv = r < N_;
        cpa16(&S.Ks[0][r][dq], &Kg[(size_t)r * HD_ + dq], mv);
        cpa16(&S.Vs[0][r][dq], &Vg[(size_t)r * HD_ + dq], mv);
    }
    cpa_commit();
    asm volatile("cp.async.wait_group 0;\n" ::: "memory");
    __syncthreads();

    unsigned qf[4][4];
#pragma unroll
    for (int kk = 0; kk < 4; kk++) {
        int K0 = kk * 8;
        qf[kk][0] = S.P2[R0 + ly][K0 + lx];
        qf[kk][1] = S.P2[R0 + ly + 8][K0 + lx];
        qf[kk][2] = S.P2[R0 + ly][K0 + lx + 4];
        qf[kk][3] = S.P2[R0 + ly + 8][K0 + lx + 4];
    }
    __syncwarp();

#pragma unroll
    for (int l = 0; l < 8; l++) {
        int idx = lane + l * 32;
        int rr = idx >> 4, cq = (idx & 15) << 2;
        cpa16(&S.P2[R0 + rr][cq], &POSg[(size_t)(q0 + R0 + rr) * N_ + cq],
              (q0 + R0 + rr < N_) && (cq < N_));
    }
    cpa_commit();   // per-thread FIFO: { P2[0] }

    float4 opat[4], opos[4];
#pragma unroll
    for (int i = 0; i < 4; i++) { opat[i] = make_float4(0.f,0.f,0.f,0.f); opos[i] = opat[i]; }
    float rs0 = 0.f, rs1 = 0.f;

    for (int it = 0; it < 12; it++) {
        int cur = it & 1;
        int nxt = (it + 1) & 1;
        int m1 = (it + 1) * 64;
        unsigned ksc = ksb0 + (unsigned)(cur * 64 * QSTR) * 4u;
#pragma unroll
        for (int l = 0; l < 4; l++) {
            int idx = t + l * 128;
            int r = idx >> 3, dq = (idx & 7) << 2;
            bool mv = m1 + r < N_;
            cpa16(&S.Ks[nxt][r][dq], &Kg[(size_t)(m1 + r) * HD_ + dq], mv);
            cpa16(&S.Vs[nxt][r][dq], &Vg[(size_t)(m1 + r) * HD_ + dq], mv);
        }
        cpa_commit();

        float4 sacc[8];
#pragma unroll
        for (int i = 0; i < 8; i++) sacc[i] = make_float4(0.f,0.f,0.f,0.f);
#pragma unroll
        for (int kk = 0; kk < 4; kk++) {
            int K0 = kk * 8;
#pragma unroll
            for (int ntp = 0; ntp < 4; ntp++) {
                unsigned addr = ksc + (((ntp * 16 + brow) * QSTR + bcol + K0) << 2);
                uint4 bb = ldm4(addr);
                mma8(sacc[ntp*2],   qf[kk][0], qf[kk][1], qf[kk][2], qf[kk][3], bb.x, bb.y);
                mma8(sacc[ntp*2+1], qf[kk][0], qf[kk][1], qf[kk][2], qf[kk][3], bb.z, bb.w);
            }
        }

#pragma unroll
        for (int nt = 0; nt < 8; nt++) {
            float ex = __expf(sacc[nt].x);
            float ey = __expf(sacc[nt].y);
            float ez = __expf(sacc[nt].z);
            float ew = __expf(sacc[nt].w);
            rs0 += ex + ey;
            rs1 += ez + ew;
            uint2 u01; u01.x = f2tf(ex); u01.y = f2tf(ey);
            uint2 u23; u23.x = f2tf(ez); u23.y = f2tf(ew);
            *(uint2*)&S.P1[R0 + ly][nt * 8 + lx * 2] = u01;
            *(uint2*)&S.P1[R0 + ly + 8][nt * 8 + lx * 2] = u23;
        }

        asm volatile("cp.async.wait_group 1;\n" ::: "memory");
        __syncwarp();

#pragma unroll
        for (int kk = 0; kk < 8; kk++) {
            int K0 = kk * 8;
            uint4 P = ldm4(p1base + ((unsigned)K0 << 2));
            uint4 C = ldm4(p2base + ((unsigned)K0 << 2));
#pragma unroll
            for (int nt = 0; nt < 4; nt++) {
                unsigned b0 = S.Vs[cur][K0 + lx][nt * 8 + ly];
                unsigned b1 = S.Vs[cur][K0 + lx + 4][nt * 8 + ly];
                mma8(opat[nt], P.x, P.y, P.z, P.w, b0, b1);
                mma8(opos[nt], C.x, C.y, C.z, C.w, b0, b1);
            }
        }
        __syncwarp();

#pragma unroll
        for (int l = 0; l < 8; l++) {
            int idx = lane + l * 32;
            int rr = idx >> 4, cq = (idx & 15) << 2;
            cpa16(&S.P2[R0 + rr][cq], &POSg[(size_t)(q0 + R0 + rr) * N_ + m1 + cq],
                  (q0 + R0 + rr < N_) && (m1 + cq < N_));
        }
        cpa_commit();
        asm volatile("cp.async.wait_group 1;\n" ::: "memory");
        __syncthreads();
    }

    // ---- peeled tail: it=12, m0=768, only 16 valid cols
    {
        unsigned ksc = ksb0;   // cur = 0
        float4 sacc[2];
        sacc[0] = make_float4(0.f,0.f,0.f,0.f);
        sacc[1] = sacc[0];
#pragma unroll
        for (int kk = 0; kk < 4; kk++) {
            int K0 = kk * 8;
            unsigned addr = ksc + (((brow) * QSTR + bcol + K0) << 2);
            uint4 bb = ldm4(addr);
            mma8(sacc[0], qf[kk][0], qf[kk][1], qf[kk][2], qf[kk][3], bb.x, bb.y);
            mma8(sacc[1], qf[kk][0], qf[kk][1], qf[kk][2], qf[kk][3], bb.z, bb.w);
        }
#pragma unroll
        for (int nt = 0; nt < 2; nt++) {
            float ex = __expf(sacc[nt].x);
            float ey = __expf(sacc[nt].y);
            float ez = __expf(sacc[nt].z);
            float ew = __expf(sacc[nt].w);
            rs0 += ex + ey;
            rs1 += ez + ew;
            uint2 u01; u01.x = f2tf(ex); u01.y = f2tf(ey);
            uint2 u23; u23.x = f2tf(ez); u23.y = f2tf(ew);
            *(uint2*)&S.P1[R0 + ly][nt * 8 + lx * 2] = u01;
            *(uint2*)&S.P1[R0 + ly + 8][nt * 8 + lx * 2] = u23;
        }
        asm volatile("cp.async.wait_group 0;\n" ::: "memory");
        __syncwarp();
#pragma unroll
        for (int kk = 0; kk < 2; kk++) {
            int K0 = kk * 8;
            uint4 P = ldm4(p1base + ((unsigned)K0 << 2));
            uint4 C = ldm4(p2base + ((unsigned)K0 << 2));
#pragma unroll
            for (int nt = 0; nt < 4; nt++) {
                unsigned b0 = S.Vs[0][K0 + lx][nt * 8 + ly];
                unsigned b1 = S.Vs[0][K0 + lx + 4][nt * 8 + ly];
                mma8(opat[nt], P.x, P.y, P.z, P.w, b0, b1);
                mma8(opos[nt], C.x, C.y, C.z, C.w, b0, b1);
            }
        }
    }

    rs0 += __shfl_xor_sync(0xffffffffu, rs0, 1);
    rs0 += __shfl_xor_sync(0xffffffffu, rs0, 2);
    rs1 += __shfl_xor_sync(0xffffffffu, rs1, 1);
    rs1 += __shfl_xor_sync(0xffffffffu, rs1, 2);
    float inv0 = (1.f - gate) / rs0;
    float inv1 = (1.f - gate) / rs1;

    int n0r = q0 + R0 + ly;
    int n1r = n0r + 8;
#pragma unroll
    for (int nt = 0; nt < 4; nt++) {
        int d = nt * 8 + lx * 2;
        if (n0r < N_) {
            float2 o;
            o.x = opat[nt].x * inv0 + gate * opos[nt].x;
            o.y = opat[nt].y * inv0 + gate * opos[nt].y;
            *(float2*)&g_att[((size_t)b * N_ + n0r) * DIM_ + h * HD_ + d] = o;
        }
        if (n1r < N_) {
            float2 o;
            o.x = opat[nt].z * inv1 + gate * opos[nt].z;
            o.y = opat[nt].w * inv1 + gate * opos[nt].w;
            *(float2*)&g_att[((size_t)b * N_ + n1r) * DIM_ + h * HD_ + d] = o;
        }
    }
}

// ---------------------------------------------------------------------------
extern "C" void kernel_launch(void* const* d_in, const int* in_sizes, int n_in,
                              void* d_out, int out_size) {
    const float* x      = (const float*)d_in[0];
    const float* Wq     = (const float*)d_in[1];
    const float* Wk     = (const float*)d_in[2];
    const float* Wv     = (const float*)d_in[3];
    const float* W_pos  = (const float*)d_in[4];
    const float* b_pos  = (const float*)d_in[5];
    const float* W_out  = (const float*)d_in[6];
    const float* b_out  = (const float*)d_in[7];
    const float* gating = (const float*)d_in[8];
    float* out = (float*)d_out;

    cudaFuncSetAttribute(attn_kernel, cudaFuncAttributeMaxDynamicSharedMemorySize,
                         (int)sizeof(ASmem));

    pos_kernel<<<H_ * N_, 256>>>(W_pos, b_pos);

    gemm_qkv<<<dim3(3 * DIM_ / 64, ROWS_ / 64), 128>>>(x, Wq, Wk, Wv);   // (18, 98)

    attn_kernel<<<dim3(13, B_ * H_), 128, sizeof(ASmem)>>>(gating);

    gemm_out<<<dim3(DIM_ / 64, ROWS_ / 64), 128>>>(W_out, b_out, out);   // (6, 98)
}